// round 2
// baseline (speedup 1.0000x reference)
#include <cuda_runtime.h>

// Problem constants
#define BB 2
#define LL 2048
#define DD 1024
#define HH 16
#define DHH 64
#define BH (BB*HH)              // 32
#define MROWS (BB*LL)           // 4096
#define OUT_ELEMS (MROWS*DD)    // 4194304
#define ATTN_ELEMS ((long)BH*LL*LL)  // 134217728
#define LN_EPS 1e-5f

// Scratch (static device globals: allowed; no runtime allocation)
__device__ float g_Q[MROWS*DD];
__device__ float g_Kp[MROWS*DD];
__device__ float g_Vp[MROWS*DD];
__device__ float g_ctx[MROWS*DD];
__device__ float g_proj[MROWS*DD];

// ---------------------------------------------------------------------------
// Generic NT GEMM: C[m,n] = alpha * sum_k A[m,k]*B[n,k]  (+ bias[n])
// A: [M,K] row-major, B: [N,K] row-major, C: [M,N] row-major.
// Batched via blockIdx.z with element strides.
// BM=BN=128, BK=16, TM=TN=8, 256 threads.
// ---------------------------------------------------------------------------
__global__ void __launch_bounds__(256) gemm_nt_kernel(
    const float* __restrict__ A, const float* __restrict__ Bm,
    const float* __restrict__ bias, float* __restrict__ C,
    int Mn, int Nn, int Kn, float alpha,
    long strideA, long strideB, long strideC)
{
    const int z = blockIdx.z;
    A  += (long)z * strideA;
    Bm += (long)z * strideB;
    C  += (long)z * strideC;

    __shared__ float As[16][128];
    __shared__ float Bs[16][128];

    const int tid = threadIdx.x;
    const int tx = tid & 15;        // 0..15 -> col group
    const int ty = tid >> 4;        // 0..15 -> row group
    const int row0 = blockIdx.y * 128;
    const int col0 = blockIdx.x * 128;

    float acc[8][8];
    #pragma unroll
    for (int i = 0; i < 8; i++)
        #pragma unroll
        for (int j = 0; j < 8; j++) acc[i][j] = 0.f;

    for (int k0 = 0; k0 < Kn; k0 += 16) {
        // Load A tile [128 x 16] transposed into As[k][m]; 512 float4s, 2/thread
        #pragma unroll
        for (int i = 0; i < 2; i++) {
            int idx = tid + i * 256;       // 0..511
            int m  = idx >> 2;             // /4
            int kq = idx & 3;
            float4 v = *reinterpret_cast<const float4*>(
                &A[(long)(row0 + m) * Kn + k0 + kq * 4]);
            As[kq*4+0][m] = v.x; As[kq*4+1][m] = v.y;
            As[kq*4+2][m] = v.z; As[kq*4+3][m] = v.w;
        }
        // Load B tile [128 x 16] transposed into Bs[k][n]
        #pragma unroll
        for (int i = 0; i < 2; i++) {
            int idx = tid + i * 256;
            int nn  = idx >> 2;
            int kq  = idx & 3;
            float4 v = *reinterpret_cast<const float4*>(
                &Bm[(long)(col0 + nn) * Kn + k0 + kq * 4]);
            Bs[kq*4+0][nn] = v.x; Bs[kq*4+1][nn] = v.y;
            Bs[kq*4+2][nn] = v.z; Bs[kq*4+3][nn] = v.w;
        }
        __syncthreads();

        #pragma unroll
        for (int k = 0; k < 16; k++) {
            float ra[8], rb[8];
            #pragma unroll
            for (int i = 0; i < 8; i++) ra[i] = As[k][ty*8 + i];
            #pragma unroll
            for (int j = 0; j < 8; j++) rb[j] = Bs[k][tx*8 + j];
            #pragma unroll
            for (int i = 0; i < 8; i++)
                #pragma unroll
                for (int j = 0; j < 8; j++)
                    acc[i][j] += ra[i] * rb[j];
        }
        __syncthreads();
    }

    float bv[8];
    #pragma unroll
    for (int j = 0; j < 8; j++)
        bv[j] = bias ? bias[col0 + tx*8 + j] : 0.f;

    #pragma unroll
    for (int i = 0; i < 8; i++) {
        long base = (long)(row0 + ty*8 + i) * Nn + col0 + tx*8;
        #pragma unroll
        for (int j = 0; j < 8; j++)
            C[base + j] = acc[i][j] * alpha + bv[j];
    }
}

// ---------------------------------------------------------------------------
// Row softmax in place: rows of length LL (2048). One block (256 thr) per row.
// ---------------------------------------------------------------------------
__device__ __forceinline__ float warp_max(float v) {
    #pragma unroll
    for (int o = 16; o > 0; o >>= 1) v = fmaxf(v, __shfl_xor_sync(0xffffffffu, v, o));
    return v;
}
__device__ __forceinline__ float warp_sum(float v) {
    #pragma unroll
    for (int o = 16; o > 0; o >>= 1) v += __shfl_xor_sync(0xffffffffu, v, o);
    return v;
}

__global__ void __launch_bounds__(256) softmax_rows_kernel(float* __restrict__ attn)
{
    float4* p4 = reinterpret_cast<float4*>(attn + (long)blockIdx.x * LL);
    const int tid = threadIdx.x;
    const int lane = tid & 31, wid = tid >> 5;
    __shared__ float red[8];

    float4 a = p4[tid];
    float4 b = p4[tid + 256];
    float m = fmaxf(fmaxf(fmaxf(a.x, a.y), fmaxf(a.z, a.w)),
                    fmaxf(fmaxf(b.x, b.y), fmaxf(b.z, b.w)));
    m = warp_max(m);
    if (lane == 0) red[wid] = m;
    __syncthreads();
    if (wid == 0) {
        float t = (lane < 8) ? red[lane] : -3.0e38f;
        t = warp_max(t);
        if (lane == 0) red[0] = t;
    }
    __syncthreads();
    const float mx = red[0];
    __syncthreads();

    a.x = __expf(a.x - mx); a.y = __expf(a.y - mx);
    a.z = __expf(a.z - mx); a.w = __expf(a.w - mx);
    b.x = __expf(b.x - mx); b.y = __expf(b.y - mx);
    b.z = __expf(b.z - mx); b.w = __expf(b.w - mx);

    float s = a.x + a.y + a.z + a.w + b.x + b.y + b.z + b.w;
    s = warp_sum(s);
    if (lane == 0) red[wid] = s;
    __syncthreads();
    if (wid == 0) {
        float t = (lane < 8) ? red[lane] : 0.f;
        t = warp_sum(t);
        if (lane == 0) red[0] = t;
    }
    __syncthreads();
    const float inv = 1.0f / red[0];

    a.x *= inv; a.y *= inv; a.z *= inv; a.w *= inv;
    b.x *= inv; b.y *= inv; b.z *= inv; b.w *= inv;
    p4[tid] = a;
    p4[tid + 256] = b;
}

// ---------------------------------------------------------------------------
// AV GEMM: ctx[n,q,c] = sum_k attn[n,q,k] * V[n,k,c]
// attn [LL,LL] row-major, V [LL,DHH] row-major. Tile: 128 q x 64 c, BK=32.
// ---------------------------------------------------------------------------
__global__ void __launch_bounds__(256) gemm_av_kernel(
    const float* __restrict__ attn, const float* __restrict__ V,
    float* __restrict__ ctx)
{
    const int z = blockIdx.z;
    const float* Ap = attn + (long)z * LL * LL;
    const float* Vp = V    + (long)z * LL * DHH;
    float*       Cp = ctx  + (long)z * LL * DHH;

    __shared__ float As[32][128];
    __shared__ float Vs[32][64];

    const int tid = threadIdx.x;
    const int tx = tid & 15;       // c group: c = tx*4
    const int ty = tid >> 4;       // q group: q = row0 + ty*8
    const int row0 = blockIdx.y * 128;

    float acc[8][4];
    #pragma unroll
    for (int i = 0; i < 8; i++)
        #pragma unroll
        for (int j = 0; j < 4; j++) acc[i][j] = 0.f;

    for (int k0 = 0; k0 < LL; k0 += 32) {
        // attn tile [128 x 32]: 1024 float4, 4/thread -> As[k][m]
        #pragma unroll
        for (int i = 0; i < 4; i++) {
            int idx = tid + i * 256;
            int m  = idx >> 3;
            int kq = idx & 7;
            float4 v = *reinterpret_cast<const float4*>(
                &Ap[(long)(row0 + m) * LL + k0 + kq * 4]);
            As[kq*4+0][m] = v.x; As[kq*4+1][m] = v.y;
            As[kq*4+2][m] = v.z; As[kq*4+3][m] = v.w;
        }
        // V tile [32 x 64]: 512 float4, 2/thread, direct layout
        #pragma unroll
        for (int i = 0; i < 2; i++) {
            int idx = tid + i * 256;
            int k  = idx >> 4;
            int cq = idx & 15;
            *reinterpret_cast<float4*>(&Vs[k][cq*4]) =
                *reinterpret_cast<const float4*>(&Vp[(long)(k0 + k) * DHH + cq*4]);
        }
        __syncthreads();

        #pragma unroll
        for (int k = 0; k < 32; k++) {
            float rb[4];
            #pragma unroll
            for (int j = 0; j < 4; j++) rb[j] = Vs[k][tx*4 + j];
            #pragma unroll
            for (int i = 0; i < 8; i++) {
                float ra = As[k][ty*8 + i];
                #pragma unroll
                for (int j = 0; j < 4; j++) acc[i][j] += ra * rb[j];
            }
        }
        __syncthreads();
    }

    #pragma unroll
    for (int i = 0; i < 8; i++) {
        float4 v = make_float4(acc[i][0], acc[i][1], acc[i][2], acc[i][3]);
        *reinterpret_cast<float4*>(&Cp[(long)(row0 + ty*8 + i) * DHH + tx*4]) = v;
    }
}

// ---------------------------------------------------------------------------
// Residual + LayerNorm: out = LN(proj + resid) * gamma + beta
// One block (256 thr) per row of D=1024.
// ---------------------------------------------------------------------------
__global__ void __launch_bounds__(256) ln_kernel(
    const float* __restrict__ proj, const float* __restrict__ resid,
    const float* __restrict__ gamma, const float* __restrict__ beta,
    float* __restrict__ out)
{
    const long row = blockIdx.x;
    const int tid = threadIdx.x;
    const int lane = tid & 31, wid = tid >> 5;
    __shared__ float red[8];

    float4 x = reinterpret_cast<const float4*>(proj + row * DD)[tid];
    float4 r = reinterpret_cast<const float4*>(resid + row * DD)[tid];
    x.x += r.x; x.y += r.y; x.z += r.z; x.w += r.w;

    float s = x.x + x.y + x.z + x.w;
    s = warp_sum(s);
    if (lane == 0) red[wid] = s;
    __syncthreads();
    if (wid == 0) {
        float t = (lane < 8) ? red[lane] : 0.f;
        t = warp_sum(t);
        if (lane == 0) red[0] = t;
    }
    __syncthreads();
    const float mu = red[0] * (1.0f / DD);
    __syncthreads();

    float dx = x.x - mu, dy = x.y - mu, dz = x.z - mu, dw = x.w - mu;
    float ss = dx*dx + dy*dy + dz*dz + dw*dw;
    ss = warp_sum(ss);
    if (lane == 0) red[wid] = ss;
    __syncthreads();
    if (wid == 0) {
        float t = (lane < 8) ? red[lane] : 0.f;
        t = warp_sum(t);
        if (lane == 0) red[0] = t;
    }
    __syncthreads();
    const float var = red[0] * (1.0f / DD);
    const float rs = rsqrtf(var + LN_EPS);

    float4 g  = reinterpret_cast<const float4*>(gamma)[tid];
    float4 be = reinterpret_cast<const float4*>(beta)[tid];
    float4 o;
    o.x = dx * rs * g.x + be.x;
    o.y = dy * rs * g.y + be.y;
    o.z = dz * rs * g.z + be.z;
    o.w = dw * rs * g.w + be.w;
    reinterpret_cast<float4*>(out + row * DD)[tid] = o;
}

// ---------------------------------------------------------------------------
// Launch
// ---------------------------------------------------------------------------
extern "C" void kernel_launch(void* const* d_in, const int* in_sizes, int n_in,
                              void* d_out, int out_size)
{
    const float* query = (const float*)d_in[0];
    const float* key   = (const float*)d_in[1];
    const float* value = (const float*)d_in[2];
    const float* Wq = (const float*)d_in[3];
    const float* bq = (const float*)d_in[4];
    const float* Wk = (const float*)d_in[5];
    const float* bk = (const float*)d_in[6];
    const float* Wv = (const float*)d_in[7];
    const float* bv = (const float*)d_in[8];
    const float* Wo = (const float*)d_in[9];
    const float* bo = (const float*)d_in[10];
    const float* gamma = (const float*)d_in[11];
    const float* beta  = (const float*)d_in[12];

    float* out  = (float*)d_out;
    float* attn = out + OUT_ELEMS;   // tuple output: [out | attention]

    float *Q, *K, *V, *ctx, *proj;
    cudaGetSymbolAddress((void**)&Q,    g_Q);
    cudaGetSymbolAddress((void**)&K,    g_Kp);
    cudaGetSymbolAddress((void**)&V,    g_Vp);
    cudaGetSymbolAddress((void**)&ctx,  g_ctx);
    cudaGetSymbolAddress((void**)&proj, g_proj);

    dim3 blk(256);

    // Q/K/V projections: [4096,1024] = [4096,1024] @ W^T
    dim3 gp(DD/128, MROWS/128, 1);   // (8, 32)
    gemm_nt_kernel<<<gp, blk>>>(query, Wq, bq, Q, MROWS, DD, DD, 1.f, 0, 0, 0);
    gemm_nt_kernel<<<gp, blk>>>(key,   Wk, bk, K, MROWS, DD, DD, 1.f, 0, 0, 0);
    gemm_nt_kernel<<<gp, blk>>>(value, Wv, bv, V, MROWS, DD, DD, 1.f, 0, 0, 0);

    // Scores (scaled) directly into d_out attention region:
    // per head-batch n: scores = Q_n @ K_n^T * 0.125   (view reshape is free)
    dim3 gs(LL/128, LL/128, BH);     // (16, 16, 32)
    gemm_nt_kernel<<<gs, blk>>>(Q, K, nullptr, attn, LL, LL, DHH, 0.125f,
                                (long)LL*DHH, (long)LL*DHH, (long)LL*LL);

    // Softmax in place over rows of 2048
    softmax_rows_kernel<<<BH * LL, blk>>>(attn);

    // context = attn @ V
    dim3 ga(1, LL/128, BH);          // (1, 16, 32)
    gemm_av_kernel<<<ga, blk>>>(attn, V, ctx);

    // Output projection (+bo), then residual+LN into d_out
    gemm_nt_kernel<<<gp, blk>>>(ctx, Wo, bo, proj, MROWS, DD, DD, 1.f, 0, 0, 0);
    ln_kernel<<<MROWS, blk>>>(proj, query, gamma, beta, out);
}

// round 4
// speedup vs baseline: 1.6419x; 1.6419x over previous
#include <cuda_runtime.h>
#include <cuda_bf16.h>
#include <cstdint>

#define BB 2
#define LL 2048
#define DD 1024
#define HH 16
#define DHH 64
#define BH (BB*HH)
#define MROWS (BB*LL)           // 4096
#define OUT_ELEMS (MROWS*DD)
#define LN_EPS 1e-5f

// ---------------------------------------------------------------------------
// Static device scratch
// ---------------------------------------------------------------------------
__device__ __nv_bfloat16 g_xq_h[MROWS*DD], g_xq_l[MROWS*DD];
__device__ __nv_bfloat16 g_xk_h[MROWS*DD], g_xk_l[MROWS*DD];
__device__ __nv_bfloat16 g_xv_h[MROWS*DD], g_xv_l[MROWS*DD];
__device__ __nv_bfloat16 g_wq_h[DD*DD], g_wq_l[DD*DD];
__device__ __nv_bfloat16 g_wk_h[DD*DD], g_wk_l[DD*DD];
__device__ __nv_bfloat16 g_wv_h[DD*DD], g_wv_l[DD*DD];
__device__ __nv_bfloat16 g_wo_h[DD*DD], g_wo_l[DD*DD];
__device__ __nv_bfloat16 g_Qh[MROWS*DD], g_Ql[MROWS*DD];
__device__ __nv_bfloat16 g_Kh[MROWS*DD], g_Kl[MROWS*DD];
__device__ __nv_bfloat16 g_Vth[MROWS*DD], g_Vtl[MROWS*DD];  // [n][c][k]
__device__ __nv_bfloat16 g_ctxh[MROWS*DD], g_ctxl[MROWS*DD];
__device__ float g_part[(long)BH*LL*16];
__device__ float g_rinv[(long)BH*LL];
__device__ float g_proj[MROWS*DD];

// ---------------------------------------------------------------------------
// PTX helpers (baseline compute_103-legal: ldmatrix + mma.sync only)
// ---------------------------------------------------------------------------
__device__ __forceinline__ uint32_t smem_u32(const void* p) {
    uint32_t a;
    asm("{ .reg .u64 t; cvta.to.shared.u64 t, %1; cvt.u32.u64 %0, t; }" : "=r"(a) : "l"(p));
    return a;
}

#define LDMX4(r0,r1,r2,r3,addr) \
    asm volatile("ldmatrix.sync.aligned.m8n8.x4.shared.b16 {%0,%1,%2,%3}, [%4];" \
        : "=r"(r0), "=r"(r1), "=r"(r2), "=r"(r3) : "r"(addr))

#define MMA_BF16(d, a, b0v, b1v) \
    asm volatile("mma.sync.aligned.m16n8k16.row.col.f32.bf16.bf16.f32 " \
        "{%0,%1,%2,%3},{%4,%5,%6,%7},{%8,%9},{%0,%1,%2,%3};" \
        : "+f"((d)[0]), "+f"((d)[1]), "+f"((d)[2]), "+f"((d)[3]) \
        : "r"((a)[0]), "r"((a)[1]), "r"((a)[2]), "r"((a)[3]), "r"(b0v), "r"(b1v))

// A fragment: row-major tile [R][40] bf16, m16k16 at (mbase, ks)
__device__ __forceinline__ void lda_frag(uint32_t a[4], const __nv_bfloat16* tile,
                                         int mbase, int ks, int lane) {
    int row = mbase + (lane & 7) + ((lane >> 3) & 1) * 8;
    int col = ks + (lane >> 4) * 8;
    uint32_t addr = smem_u32(reinterpret_cast<const char*>(tile) + row * 80 + col * 2);
    LDMX4(a[0], a[1], a[2], a[3], addr);
}

// B fragments (2x n8k16) from [N][40] tile at (nbase, ks): b[0..1]=n0-7, b[2..3]=n8-15
__device__ __forceinline__ void ldb_frag(uint32_t b[4], const __nv_bfloat16* tile,
                                         int nbase, int ks, int lane) {
    int r = lane & 7, gp = lane >> 3;
    int n = nbase + (gp >> 1) * 8 + r;
    int col = ks + (gp & 1) * 8;
    uint32_t addr = smem_u32(reinterpret_cast<const char*>(tile) + n * 80 + col * 2);
    LDMX4(b[0], b[1], b[2], b[3], addr);
}

// Load R rows x 32 bf16 from global (row stride ld) into smem tile [R][40]
__device__ __forceinline__ void load32(const __nv_bfloat16* __restrict__ src, long ld,
                                       int R, __nv_bfloat16* tile, int tid) {
    char* t = reinterpret_cast<char*>(tile);
    for (int i = tid; i < R * 4; i += 256) {
        int row = i >> 2, q = i & 3;
        uint4 v = *reinterpret_cast<const uint4*>(src + (long)row * ld + q * 8);
        *reinterpret_cast<uint4*>(t + row * 80 + q * 16) = v;
    }
}

__device__ __forceinline__ void split2(float v, unsigned short& h, unsigned short& l) {
    __nv_bfloat16 bh = __float2bfloat16(v);
    __nv_bfloat16 bl = __float2bfloat16(v - __bfloat162float(bh));
    h = __bfloat16_as_ushort(bh); l = __bfloat16_as_ushort(bl);
}

// ---------------------------------------------------------------------------
// fp32 -> (hi,lo) bf16 split
// ---------------------------------------------------------------------------
__global__ void __launch_bounds__(256) split_kernel(const float* __restrict__ src,
                                                    __nv_bfloat16* __restrict__ hi,
                                                    __nv_bfloat16* __restrict__ lo) {
    long i = (long)blockIdx.x * 256 + threadIdx.x;
    float4 v = reinterpret_cast<const float4*>(src)[i];
    unsigned short h0,h1,h2,h3,l0,l1,l2,l3;
    split2(v.x,h0,l0); split2(v.y,h1,l1); split2(v.z,h2,l2); split2(v.w,h3,l3);
    uint2 uh, ul;
    uh.x = (uint32_t)h0 | ((uint32_t)h1 << 16); uh.y = (uint32_t)h2 | ((uint32_t)h3 << 16);
    ul.x = (uint32_t)l0 | ((uint32_t)l1 << 16); ul.y = (uint32_t)l2 | ((uint32_t)l3 << 16);
    reinterpret_cast<uint2*>(hi)[i] = uh;
    reinterpret_cast<uint2*>(lo)[i] = ul;
}

// ---------------------------------------------------------------------------
// Projection GEMM (split-bf16 mma.sync): C = A @ B^T + bias
// Block 128x128, BK=32, warps 2x4 (warp tile 64x32).
// mode 0: bf16 hi/lo flat; mode 1: Vt scatter; mode 2: fp32 out
// ---------------------------------------------------------------------------
__global__ void __launch_bounds__(256) proj_mma_kernel(
    const __nv_bfloat16* __restrict__ Ahi, const __nv_bfloat16* __restrict__ Alo,
    const __nv_bfloat16* __restrict__ Bhi, const __nv_bfloat16* __restrict__ Blo,
    const float* __restrict__ bias,
    __nv_bfloat16* __restrict__ OutHi, __nv_bfloat16* __restrict__ OutLo,
    float* __restrict__ OutF, int mode)
{
    __shared__ __align__(16) __nv_bfloat16 sAh[128*40], sAl[128*40];
    __shared__ __align__(16) __nv_bfloat16 sBh[128*40], sBl[128*40];

    const int tid = threadIdx.x, wid = tid >> 5, lane = tid & 31;
    const int row0 = blockIdx.y * 128, col0 = blockIdx.x * 128;
    const int wm = (wid >> 2) * 64, wn = (wid & 3) * 32;

    float acc[4][4][4];
    #pragma unroll
    for (int i = 0; i < 4; i++)
        #pragma unroll
        for (int j = 0; j < 4; j++)
            #pragma unroll
            for (int q = 0; q < 4; q++) acc[i][j][q] = 0.f;

    for (int c = 0; c < DD / 32; c++) {
        __syncthreads();
        load32(Ahi + (long)row0 * DD + c * 32, DD, 128, sAh, tid);
        load32(Alo + (long)row0 * DD + c * 32, DD, 128, sAl, tid);
        load32(Bhi + (long)col0 * DD + c * 32, DD, 128, sBh, tid);
        load32(Blo + (long)col0 * DD + c * 32, DD, 128, sBl, tid);
        __syncthreads();

        #pragma unroll
        for (int ks = 0; ks < 32; ks += 16) {
            uint32_t ah[4][4], al[4][4], bh[2][4], bl[2][4];
            #pragma unroll
            for (int mf = 0; mf < 4; mf++) {
                lda_frag(ah[mf], sAh, wm + mf*16, ks, lane);
                lda_frag(al[mf], sAl, wm + mf*16, ks, lane);
            }
            ldb_frag(bh[0], sBh, wn,      ks, lane);
            ldb_frag(bh[1], sBh, wn + 16, ks, lane);
            ldb_frag(bl[0], sBl, wn,      ks, lane);
            ldb_frag(bl[1], sBl, wn + 16, ks, lane);
            #pragma unroll
            for (int mf = 0; mf < 4; mf++)
                #pragma unroll
                for (int nf = 0; nf < 4; nf++) {
                    MMA_BF16(acc[mf][nf], ah[mf], bh[nf>>1][(nf&1)*2], bh[nf>>1][(nf&1)*2+1]);
                    MMA_BF16(acc[mf][nf], ah[mf], bl[nf>>1][(nf&1)*2], bl[nf>>1][(nf&1)*2+1]);
                    MMA_BF16(acc[mf][nf], al[mf], bh[nf>>1][(nf&1)*2], bh[nf>>1][(nf&1)*2+1]);
                }
        }
    }

    const int g = lane >> 2, tq = lane & 3;
    #pragma unroll
    for (int mf = 0; mf < 4; mf++) {
        #pragma unroll
        for (int nf = 0; nf < 4; nf++) {
            long r0 = row0 + wm + mf*16 + g, r1 = r0 + 8;
            int  cb = col0 + wn + nf*8 + tq*2;
            float b0 = bias[cb], b1 = bias[cb + 1];
            float v00 = acc[mf][nf][0] + b0, v01 = acc[mf][nf][1] + b1;
            float v10 = acc[mf][nf][2] + b0, v11 = acc[mf][nf][3] + b1;
            if (mode == 2) {
                *reinterpret_cast<float2*>(OutF + r0 * DD + cb) = make_float2(v00, v01);
                *reinterpret_cast<float2*>(OutF + r1 * DD + cb) = make_float2(v10, v11);
            } else if (mode == 0) {
                unsigned short h0,h1,l0,l1;
                split2(v00,h0,l0); split2(v01,h1,l1);
                *reinterpret_cast<uint32_t*>(OutHi + r0*DD + cb) = (uint32_t)h0 | ((uint32_t)h1<<16);
                *reinterpret_cast<uint32_t*>(OutLo + r0*DD + cb) = (uint32_t)l0 | ((uint32_t)l1<<16);
                split2(v10,h0,l0); split2(v11,h1,l1);
                *reinterpret_cast<uint32_t*>(OutHi + r1*DD + cb) = (uint32_t)h0 | ((uint32_t)h1<<16);
                *reinterpret_cast<uint32_t*>(OutLo + r1*DD + cb) = (uint32_t)l0 | ((uint32_t)l1<<16);
            } else {
                #pragma unroll
                for (int e = 0; e < 4; e++) {
                    long rr = (e < 2) ? r0 : r1;
                    int  cc = cb + (e & 1);
                    float v = (e==0)?v00:(e==1)?v01:(e==2)?v10:v11;
                    unsigned short h, l; split2(v, h, l);
                    long f = rr * DD + cc;
                    long n = f >> 17, rem = f & 131071;
                    long kpos = rem >> 6, cdim = rem & 63;
                    long addr = n * 131072 + cdim * 2048 + kpos;
                    OutHi[addr] = __ushort_as_bfloat16(h);
                    OutLo[addr] = __ushort_as_bfloat16(l);
                }
            }
        }
    }
}

// ---------------------------------------------------------------------------
// Scores: per head, 128x128 tile, K=64. Epilogue: exp(s/8) -> attn, row partials.
// ---------------------------------------------------------------------------
__global__ void __launch_bounds__(256) scores_mma_kernel(
    const __nv_bfloat16* __restrict__ Qhi, const __nv_bfloat16* __restrict__ Qlo,
    const __nv_bfloat16* __restrict__ Khi, const __nv_bfloat16* __restrict__ Klo,
    float* __restrict__ attn, float* __restrict__ part)
{
    __shared__ __align__(16) __nv_bfloat16 sAh[128*40], sAl[128*40];
    __shared__ __align__(16) __nv_bfloat16 sBh[128*40], sBl[128*40];
    __shared__ float srow[128][4];

    const int tid = threadIdx.x, wid = tid >> 5, lane = tid & 31;
    const int z = blockIdx.z;
    const int row0 = blockIdx.y * 128, col0 = blockIdx.x * 128;
    const int wm = (wid >> 2) * 64, wn = (wid & 3) * 32;
    const long hoff = (long)z * LL * DHH;

    float acc[4][4][4];
    #pragma unroll
    for (int i = 0; i < 4; i++)
        #pragma unroll
        for (int j = 0; j < 4; j++)
            #pragma unroll
            for (int q = 0; q < 4; q++) acc[i][j][q] = 0.f;

    for (int c = 0; c < 2; c++) {
        __syncthreads();
        load32(Qhi + hoff + (long)row0 * 64 + c * 32, 64, 128, sAh, tid);
        load32(Qlo + hoff + (long)row0 * 64 + c * 32, 64, 128, sAl, tid);
        load32(Khi + hoff + (long)col0 * 64 + c * 32, 64, 128, sBh, tid);
        load32(Klo + hoff + (long)col0 * 64 + c * 32, 64, 128, sBl, tid);
        __syncthreads();

        #pragma unroll
        for (int ks = 0; ks < 32; ks += 16) {
            uint32_t ah[4][4], al[4][4], bh[2][4], bl[2][4];
            #pragma unroll
            for (int mf = 0; mf < 4; mf++) {
                lda_frag(ah[mf], sAh, wm + mf*16, ks, lane);
                lda_frag(al[mf], sAl, wm + mf*16, ks, lane);
            }
            ldb_frag(bh[0], sBh, wn,      ks, lane);
            ldb_frag(bh[1], sBh, wn + 16, ks, lane);
            ldb_frag(bl[0], sBl, wn,      ks, lane);
            ldb_frag(bl[1], sBl, wn + 16, ks, lane);
            #pragma unroll
            for (int mf = 0; mf < 4; mf++)
                #pragma unroll
                for (int nf = 0; nf < 4; nf++) {
                    MMA_BF16(acc[mf][nf], ah[mf], bh[nf>>1][(nf&1)*2], bh[nf>>1][(nf&1)*2+1]);
                    MMA_BF16(acc[mf][nf], ah[mf], bl[nf>>1][(nf&1)*2], bl[nf>>1][(nf&1)*2+1]);
                    MMA_BF16(acc[mf][nf], al[mf], bh[nf>>1][(nf&1)*2], bh[nf>>1][(nf&1)*2+1]);
                }
        }
    }

    const int g = lane >> 2, tq = lane & 3;
    float* ap = attn + (long)z * LL * LL;
    #pragma unroll
    for (int mf = 0; mf < 4; mf++) {
        float s0 = 0.f, s1 = 0.f;
        long r0 = row0 + wm + mf*16 + g, r1 = r0 + 8;
        #pragma unroll
        for (int nf = 0; nf < 4; nf++) {
            int cb = col0 + wn + nf*8 + tq*2;
            float e00 = __expf(acc[mf][nf][0] * 0.125f);
            float e01 = __expf(acc[mf][nf][1] * 0.125f);
            float e10 = __expf(acc[mf][nf][2] * 0.125f);
            float e11 = __expf(acc[mf][nf][3] * 0.125f);
            s0 += e00 + e01; s1 += e10 + e11;
            *reinterpret_cast<float2*>(ap + r0 * LL + cb) = make_float2(e00, e01);
            *reinterpret_cast<float2*>(ap + r1 * LL + cb) = make_float2(e10, e11);
        }
        s0 += __shfl_xor_sync(0xffffffffu, s0, 1);
        s0 += __shfl_xor_sync(0xffffffffu, s0, 2);
        s1 += __shfl_xor_sync(0xffffffffu, s1, 1);
        s1 += __shfl_xor_sync(0xffffffffu, s1, 2);
        if (tq == 0) {
            srow[wm + mf*16 + g][wid & 3]     = s0;
            srow[wm + mf*16 + g + 8][wid & 3] = s1;
        }
    }
    __syncthreads();
    if (tid < 128) {
        float t = srow[tid][0] + srow[tid][1] + srow[tid][2] + srow[tid][3];
        part[((long)z * LL + row0 + tid) * 16 + blockIdx.x] = t;
    }
}

// ---------------------------------------------------------------------------
// Row reciprocal
// ---------------------------------------------------------------------------
__global__ void __launch_bounds__(256) rowinv_kernel(const float* __restrict__ part,
                                                     float* __restrict__ rinv) {
    long i = (long)blockIdx.x * 256 + threadIdx.x;
    float s = 0.f;
    #pragma unroll
    for (int t = 0; t < 16; t++) s += part[i * 16 + t];
    rinv[i] = 1.0f / s;
}

// ---------------------------------------------------------------------------
// AV: normalize attn in place, split to bf16, tensor MMA vs Vt. Block 128x64.
// ---------------------------------------------------------------------------
__global__ void __launch_bounds__(256) av_mma_kernel(
    float* __restrict__ attn,
    const __nv_bfloat16* __restrict__ Vthi, const __nv_bfloat16* __restrict__ Vtlo,
    const float* __restrict__ rinv,
    __nv_bfloat16* __restrict__ CtxHi, __nv_bfloat16* __restrict__ CtxLo)
{
    __shared__ __align__(16) __nv_bfloat16 sAh[128*40], sAl[128*40];
    __shared__ __align__(16) __nv_bfloat16 sBh[64*40], sBl[64*40];

    const int tid = threadIdx.x, wid = tid >> 5, lane = tid & 31;
    const int z = blockIdx.y;
    const int row0 = blockIdx.x * 128;
    const int wm = (wid >> 2) * 64, wn = (wid & 3) * 16;

    float* ab = attn + (long)z * LL * LL + (long)row0 * LL;
    const float* rv = rinv + (long)z * LL + row0;
    const __nv_bfloat16* vh = Vthi + (long)z * LL * DHH;
    const __nv_bfloat16* vl = Vtlo + (long)z * LL * DHH;

    float acc[4][2][4];
    #pragma unroll
    for (int i = 0; i < 4; i++)
        #pragma unroll
        for (int j = 0; j < 2; j++)
            #pragma unroll
            for (int q = 0; q < 4; q++) acc[i][j][q] = 0.f;

    char* pAh = reinterpret_cast<char*>(sAh);
    char* pAl = reinterpret_cast<char*>(sAl);

    for (int c = 0; c < LL / 32; c++) {
        __syncthreads();
        // normalize 128x32 fp32 attn chunk, write back, split into smem
        for (int i = tid; i < 1024; i += 256) {
            int row = i >> 3, q = i & 7;
            long off = (long)row * LL + c * 32 + q * 4;
            float4 v = *reinterpret_cast<const float4*>(ab + off);
            float r = rv[row];
            v.x *= r; v.y *= r; v.z *= r; v.w *= r;
            *reinterpret_cast<float4*>(ab + off) = v;
            unsigned short h0,h1,h2,h3,l0,l1,l2,l3;
            split2(v.x,h0,l0); split2(v.y,h1,l1); split2(v.z,h2,l2); split2(v.w,h3,l3);
            uint2 uh, ul;
            uh.x = (uint32_t)h0 | ((uint32_t)h1 << 16);
            uh.y = (uint32_t)h2 | ((uint32_t)h3 << 16);
            ul.x = (uint32_t)l0 | ((uint32_t)l1 << 16);
            ul.y = (uint32_t)l2 | ((uint32_t)l3 << 16);
            *reinterpret_cast<uint2*>(pAh + row * 80 + q * 8) = uh;
            *reinterpret_cast<uint2*>(pAl + row * 80 + q * 8) = ul;
        }
        load32(vh + c * 32, LL, 64, sBh, tid);
        load32(vl + c * 32, LL, 64, sBl, tid);
        __syncthreads();

        #pragma unroll
        for (int ks = 0; ks < 32; ks += 16) {
            uint32_t ah[4][4], al[4][4], bh[4], bl[4];
            #pragma unroll
            for (int mf = 0; mf < 4; mf++) {
                lda_frag(ah[mf], sAh, wm + mf*16, ks, lane);
                lda_frag(al[mf], sAl, wm + mf*16, ks, lane);
            }
            ldb_frag(bh, sBh, wn, ks, lane);
            ldb_frag(bl, sBl, wn, ks, lane);
            #pragma unroll
            for (int mf = 0; mf < 4; mf++)
                #pragma unroll
                for (int nf = 0; nf < 2; nf++) {
                    MMA_BF16(acc[mf][nf], ah[mf], bh[nf*2], bh[nf*2+1]);
                    MMA_BF16(acc[mf][nf], ah[mf], bl[nf*2], bl[nf*2+1]);
                    MMA_BF16(acc[mf][nf], al[mf], bh[nf*2], bh[nf*2+1]);
                }
        }
    }

    const int g = lane >> 2, tq = lane & 3;
    #pragma unroll
    for (int mf = 0; mf < 4; mf++)
        #pragma unroll
        for (int nf = 0; nf < 2; nf++) {
            long r0 = row0 + wm + mf*16 + g, r1 = r0 + 8;
            int cb = wn + nf*8 + tq*2;
            unsigned short h0,h1,l0,l1;
            long o0 = (long)z * LL * DHH + r0 * 64 + cb;
            long o1 = (long)z * LL * DHH + r1 * 64 + cb;
            split2(acc[mf][nf][0], h0, l0); split2(acc[mf][nf][1], h1, l1);
            *reinterpret_cast<uint32_t*>(CtxHi + o0) = (uint32_t)h0 | ((uint32_t)h1<<16);
            *reinterpret_cast<uint32_t*>(CtxLo + o0) = (uint32_t)l0 | ((uint32_t)l1<<16);
            split2(acc[mf][nf][2], h0, l0); split2(acc[mf][nf][3], h1, l1);
            *reinterpret_cast<uint32_t*>(CtxHi + o1) = (uint32_t)h0 | ((uint32_t)h1<<16);
            *reinterpret_cast<uint32_t*>(CtxLo + o1) = (uint32_t)l0 | ((uint32_t)l1<<16);
        }
}

// ---------------------------------------------------------------------------
// Residual + LayerNorm
// ---------------------------------------------------------------------------
__device__ __forceinline__ float warp_sum(float v) {
    #pragma unroll
    for (int o = 16; o > 0; o >>= 1) v += __shfl_xor_sync(0xffffffffu, v, o);
    return v;
}

__global__ void __launch_bounds__(256) ln_kernel(
    const float* __restrict__ proj, const float* __restrict__ resid,
    const float* __restrict__ gamma, const float* __restrict__ beta,
    float* __restrict__ out)
{
    const long row = blockIdx.x;
    const int tid = threadIdx.x, lane = tid & 31, wid = tid >> 5;
    __shared__ float red[8];

    float4 x = reinterpret_cast<const float4*>(proj + row * DD)[tid];
    float4 r = reinterpret_cast<const float4*>(resid + row * DD)[tid];
    x.x += r.x; x.y += r.y; x.z += r.z; x.w += r.w;

    float s = warp_sum(x.x + x.y + x.z + x.w);
    if (lane == 0) red[wid] = s;
    __syncthreads();
    if (wid == 0) {
        float t = (lane < 8) ? red[lane] : 0.f;
        t = warp_sum(t);
        if (lane == 0) red[0] = t;
    }
    __syncthreads();
    const float mu = red[0] * (1.0f / DD);
    __syncthreads();

    float dx = x.x - mu, dy = x.y - mu, dz = x.z - mu, dw = x.w - mu;
    float ss = warp_sum(dx*dx + dy*dy + dz*dz + dw*dw);
    if (lane == 0) red[wid] = ss;
    __syncthreads();
    if (wid == 0) {
        float t = (lane < 8) ? red[lane] : 0.f;
        t = warp_sum(t);
        if (lane == 0) red[0] = t;
    }
    __syncthreads();
    const float rs = rsqrtf(red[0] * (1.0f / DD) + LN_EPS);

    float4 gm = reinterpret_cast<const float4*>(gamma)[tid];
    float4 be = reinterpret_cast<const float4*>(beta)[tid];
    float4 o;
    o.x = dx * rs * gm.x + be.x;
    o.y = dy * rs * gm.y + be.y;
    o.z = dz * rs * gm.z + be.z;
    o.w = dw * rs * gm.w + be.w;
    reinterpret_cast<float4*>(out + row * DD)[tid] = o;
}

// ---------------------------------------------------------------------------
// Launch
// ---------------------------------------------------------------------------
extern "C" void kernel_launch(void* const* d_in, const int* in_sizes, int n_in,
                              void* d_out, int out_size)
{
    const float* query = (const float*)d_in[0];
    const float* key   = (const float*)d_in[1];
    const float* value = (const float*)d_in[2];
    const float* Wq = (const float*)d_in[3];
    const float* bq = (const float*)d_in[4];
    const float* Wk = (const float*)d_in[5];
    const float* bk = (const float*)d_in[6];
    const float* Wv = (const float*)d_in[7];
    const float* bv = (const float*)d_in[8];
    const float* Wo = (const float*)d_in[9];
    const float* bo = (const float*)d_in[10];
    const float* gamma = (const float*)d_in[11];
    const float* beta  = (const float*)d_in[12];

    float* out  = (float*)d_out;
    float* attn = out + OUT_ELEMS;

    __nv_bfloat16 *xqh,*xql,*xkh,*xkl,*xvh,*xvl;
    __nv_bfloat16 *wqh,*wql,*wkh,*wkl,*wvh,*wvl,*woh,*wol;
    __nv_bfloat16 *Qh,*Ql,*Kh,*Kl,*Vth,*Vtl,*ch,*cl;
    float *part,*rinv,*proj;
    cudaGetSymbolAddress((void**)&xqh, g_xq_h); cudaGetSymbolAddress((void**)&xql, g_xq_l);
    cudaGetSymbolAddress((void**)&xkh, g_xk_h); cudaGetSymbolAddress((void**)&xkl, g_xk_l);
    cudaGetSymbolAddress((void**)&xvh, g_xv_h); cudaGetSymbolAddress((void**)&xvl, g_xv_l);
    cudaGetSymbolAddress((void**)&wqh, g_wq_h); cudaGetSymbolAddress((void**)&wql, g_wq_l);
    cudaGetSymbolAddress((void**)&wkh, g_wk_h); cudaGetSymbolAddress((void**)&wkl, g_wk_l);
    cudaGetSymbolAddress((void**)&wvh, g_wv_h); cudaGetSymbolAddress((void**)&wvl, g_wv_l);
    cudaGetSymbolAddress((void**)&woh, g_wo_h); cudaGetSymbolAddress((void**)&wol, g_wo_l);
    cudaGetSymbolAddress((void**)&Qh,  g_Qh);   cudaGetSymbolAddress((void**)&Ql,  g_Ql);
    cudaGetSymbolAddress((void**)&Kh,  g_Kh);   cudaGetSymbolAddress((void**)&Kl,  g_Kl);
    cudaGetSymbolAddress((void**)&Vth, g_Vth);  cudaGetSymbolAddress((void**)&Vtl, g_Vtl);
    cudaGetSymbolAddress((void**)&ch,  g_ctxh); cudaGetSymbolAddress((void**)&cl,  g_ctxl);
    cudaGetSymbolAddress((void**)&part, g_part);
    cudaGetSymbolAddress((void**)&rinv, g_rinv);
    cudaGetSymbolAddress((void**)&proj, g_proj);

    // 1) fp32 -> split bf16
    split_kernel<<<OUT_ELEMS/1024, 256>>>(query, xqh, xql);
    split_kernel<<<OUT_ELEMS/1024, 256>>>(key,   xkh, xkl);
    split_kernel<<<OUT_ELEMS/1024, 256>>>(value, xvh, xvl);
    split_kernel<<<DD*DD/1024, 256>>>(Wq, wqh, wql);
    split_kernel<<<DD*DD/1024, 256>>>(Wk, wkh, wkl);
    split_kernel<<<DD*DD/1024, 256>>>(Wv, wvh, wvl);
    split_kernel<<<DD*DD/1024, 256>>>(Wo, woh, wol);

    // 2) Projections
    dim3 gp(DD/128, MROWS/128);
    proj_mma_kernel<<<gp, 256>>>(xqh, xql, wqh, wql, bq, Qh, Ql, nullptr, 0);
    proj_mma_kernel<<<gp, 256>>>(xkh, xkl, wkh, wkl, bk, Kh, Kl, nullptr, 0);
    proj_mma_kernel<<<gp, 256>>>(xvh, xvl, wvh, wvl, bv, Vth, Vtl, nullptr, 1);

    // 3) Scores + exp + partial sums
    dim3 gs(LL/128, LL/128, BH);
    scores_mma_kernel<<<gs, 256>>>(Qh, Ql, Kh, Kl, attn, part);

    // 4) Row reciprocals
    rowinv_kernel<<<(BH*LL)/256, 256>>>(part, rinv);

    // 5) AV (normalizes attention in place, writes ctx hi/lo)
    dim3 ga(LL/128, BH);
    av_mma_kernel<<<ga, 256>>>(attn, Vth, Vtl, rinv, ch, cl);

    // 6) Out projection + residual + LN
    proj_mma_kernel<<<gp, 256>>>(ch, cl, woh, wol, bo, nullptr, nullptr, proj, 2);
    ln_kernel<<<MROWS, 256>>>(proj, query, gamma, beta, out);
}

// round 7
// speedup vs baseline: 2.6338x; 1.6042x over previous
#include <cuda_runtime.h>
#include <cuda_bf16.h>
#include <cstdint>

#define BB 2
#define LL 2048
#define DD 1024
#define HH 16
#define DHH 64
#define BH (BB*HH)
#define MROWS (BB*LL)           // 4096
#define OUT_ELEMS (MROWS*DD)
#define LN_EPS 1e-5f

// ---------------------------------------------------------------------------
// Static device scratch
// ---------------------------------------------------------------------------
__device__ __nv_bfloat16 g_xq_h[MROWS*DD], g_xq_l[MROWS*DD];
__device__ __nv_bfloat16 g_xk_h[MROWS*DD], g_xk_l[MROWS*DD];
__device__ __nv_bfloat16 g_xv_h[MROWS*DD], g_xv_l[MROWS*DD];
__device__ __nv_bfloat16 g_wq_h[DD*DD], g_wq_l[DD*DD];
__device__ __nv_bfloat16 g_wk_h[DD*DD], g_wk_l[DD*DD];
__device__ __nv_bfloat16 g_wv_h[DD*DD], g_wv_l[DD*DD];
__device__ __nv_bfloat16 g_wo_h[DD*DD], g_wo_l[DD*DD];
__device__ __nv_bfloat16 g_Qh[MROWS*DD], g_Ql[MROWS*DD];
__device__ __nv_bfloat16 g_Kh[MROWS*DD], g_Kl[MROWS*DD];
__device__ __nv_bfloat16 g_Vth[MROWS*DD], g_Vtl[MROWS*DD];  // [n][c][k]
__device__ __nv_bfloat16 g_ctxh[MROWS*DD], g_ctxl[MROWS*DD];
__device__ float g_part[(long)BH*LL*16];
__device__ float g_rinv[(long)BH*LL];
__device__ float g_proj[MROWS*DD];

// ---------------------------------------------------------------------------
// PTX helpers (baseline compute_103-legal: ldmatrix + mma.sync + cp.async)
// ---------------------------------------------------------------------------
__device__ __forceinline__ uint32_t smem_u32(const void* p) {
    uint32_t a;
    asm("{ .reg .u64 t; cvta.to.shared.u64 t, %1; cvt.u32.u64 %0, t; }" : "=r"(a) : "l"(p));
    return a;
}

#define LDMX4(r0,r1,r2,r3,addr) \
    asm volatile("ldmatrix.sync.aligned.m8n8.x4.shared.b16 {%0,%1,%2,%3}, [%4];" \
        : "=r"(r0), "=r"(r1), "=r"(r2), "=r"(r3) : "r"(addr))

#define MMA_BF16(d, a, b0v, b1v) \
    asm volatile("mma.sync.aligned.m16n8k16.row.col.f32.bf16.bf16.f32 " \
        "{%0,%1,%2,%3},{%4,%5,%6,%7},{%8,%9},{%0,%1,%2,%3};" \
        : "+f"((d)[0]), "+f"((d)[1]), "+f"((d)[2]), "+f"((d)[3]) \
        : "r"((a)[0]), "r"((a)[1]), "r"((a)[2]), "r"((a)[3]), "r"(b0v), "r"(b1v))

__device__ __forceinline__ void cp16(uint32_t dst, const void* src) {
    asm volatile("cp.async.cg.shared.global [%0], [%1], 16;" :: "r"(dst), "l"(src));
}
#define CP_COMMIT() asm volatile("cp.async.commit_group;" ::: "memory")
#define CP_WAIT0()  asm volatile("cp.async.wait_group 0;" ::: "memory")
#define CP_WAIT1()  asm volatile("cp.async.wait_group 1;" ::: "memory")

// A fragment from tile with 80B row stride at (mbase, ks)
__device__ __forceinline__ void lda_frag(uint32_t a[4], uint32_t base, int mbase, int ks, int lane) {
    int row = mbase + (lane & 7) + ((lane >> 3) & 1) * 8;
    int col = ks + (lane >> 4) * 8;
    LDMX4(a[0], a[1], a[2], a[3], base + row * 80 + col * 2);
}
// B fragments (2x n8k16): b[0..1]=n0-7, b[2..3]=n8-15
__device__ __forceinline__ void ldb_frag(uint32_t b[4], uint32_t base, int nbase, int ks, int lane) {
    int r = lane & 7, gp = lane >> 3;
    int n = nbase + (gp >> 1) * 8 + r;
    int col = ks + (gp & 1) * 8;
    LDMX4(b[0], b[1], b[2], b[3], base + n * 80 + col * 2);
}

// async copy R rows x 32 bf16 (64B) into tile with 80B row stride
__device__ __forceinline__ void load32_async(const __nv_bfloat16* __restrict__ src, long ld,
                                             int R, uint32_t base, int tid) {
    for (int i = tid; i < R * 4; i += 256) {
        int row = i >> 2, q = i & 3;
        cp16(base + row * 80 + q * 16, src + (long)row * ld + q * 8);
    }
}

__device__ __forceinline__ void split2(float v, unsigned short& h, unsigned short& l) {
    __nv_bfloat16 bh = __float2bfloat16(v);
    __nv_bfloat16 bl = __float2bfloat16(v - __bfloat162float(bh));
    h = __bfloat16_as_ushort(bh); l = __bfloat16_as_ushort(bl);
}

// ---------------------------------------------------------------------------
// fp32 -> (hi,lo) bf16 split
// ---------------------------------------------------------------------------
__global__ void __launch_bounds__(256) split_kernel(const float* __restrict__ src,
                                                    __nv_bfloat16* __restrict__ hi,
                                                    __nv_bfloat16* __restrict__ lo) {
    long i = (long)blockIdx.x * 256 + threadIdx.x;
    float4 v = reinterpret_cast<const float4*>(src)[i];
    unsigned short h0,h1,h2,h3,l0,l1,l2,l3;
    split2(v.x,h0,l0); split2(v.y,h1,l1); split2(v.z,h2,l2); split2(v.w,h3,l3);
    uint2 uh, ul;
    uh.x = (uint32_t)h0 | ((uint32_t)h1 << 16); uh.y = (uint32_t)h2 | ((uint32_t)h3 << 16);
    ul.x = (uint32_t)l0 | ((uint32_t)l1 << 16); ul.y = (uint32_t)l2 | ((uint32_t)l3 << 16);
    reinterpret_cast<uint2*>(hi)[i] = uh;
    reinterpret_cast<uint2*>(lo)[i] = ul;
}

// ---------------------------------------------------------------------------
// Projection GEMM, cp.async 2-stage: C = A @ B^T + bias
// Block 128x128, BK=32, warps 2x4 (warp tile 64x32).
// Stage layout (40960B): Ah(10240) Al Bh Bl
// ---------------------------------------------------------------------------
#define PROJ_DSMEM (2*40960)
__global__ void __launch_bounds__(256) proj_mma_kernel(
    const __nv_bfloat16* __restrict__ Ahi, const __nv_bfloat16* __restrict__ Alo,
    const __nv_bfloat16* __restrict__ Bhi, const __nv_bfloat16* __restrict__ Blo,
    const float* __restrict__ bias,
    __nv_bfloat16* __restrict__ OutHi, __nv_bfloat16* __restrict__ OutLo,
    float* __restrict__ OutF, int mode)
{
    extern __shared__ __align__(16) char smem[];
    const uint32_t sb = smem_u32(smem);
    const int tid = threadIdx.x, wid = tid >> 5, lane = tid & 31;
    const int row0 = blockIdx.y * 128, col0 = blockIdx.x * 128;
    const int wm = (wid >> 2) * 64, wn = (wid & 3) * 32;

    float acc[4][4][4];
    #pragma unroll
    for (int i = 0; i < 4; i++)
        #pragma unroll
        for (int j = 0; j < 4; j++)
            #pragma unroll
            for (int q = 0; q < 4; q++) acc[i][j][q] = 0.f;

    const __nv_bfloat16* Abase_h = Ahi + (long)row0 * DD;
    const __nv_bfloat16* Abase_l = Alo + (long)row0 * DD;
    const __nv_bfloat16* Bbase_h = Bhi + (long)col0 * DD;
    const __nv_bfloat16* Bbase_l = Blo + (long)col0 * DD;

    // prologue: stage 0
    {
        uint32_t s0 = sb;
        load32_async(Abase_h, DD, 128, s0,         tid);
        load32_async(Abase_l, DD, 128, s0 + 10240, tid);
        load32_async(Bbase_h, DD, 128, s0 + 20480, tid);
        load32_async(Bbase_l, DD, 128, s0 + 30720, tid);
        CP_COMMIT();
    }

    const int NC = DD / 32;   // 32
    for (int c = 0; c < NC; c++) {
        CP_WAIT0();
        __syncthreads();
        if (c + 1 < NC) {
            uint32_t sn = sb + ((c + 1) & 1) * 40960;
            load32_async(Abase_h + (c+1)*32, DD, 128, sn,         tid);
            load32_async(Abase_l + (c+1)*32, DD, 128, sn + 10240, tid);
            load32_async(Bbase_h + (c+1)*32, DD, 128, sn + 20480, tid);
            load32_async(Bbase_l + (c+1)*32, DD, 128, sn + 30720, tid);
            CP_COMMIT();
        }
        uint32_t sc = sb + (c & 1) * 40960;
        uint32_t sAh = sc, sAl = sc + 10240, sBh = sc + 20480, sBl = sc + 30720;

        #pragma unroll
        for (int ks = 0; ks < 32; ks += 16) {
            uint32_t ah[4][4], al[4][4], bh[2][4], bl[2][4];
            #pragma unroll
            for (int mf = 0; mf < 4; mf++) {
                lda_frag(ah[mf], sAh, wm + mf*16, ks, lane);
                lda_frag(al[mf], sAl, wm + mf*16, ks, lane);
            }
            ldb_frag(bh[0], sBh, wn,      ks, lane);
            ldb_frag(bh[1], sBh, wn + 16, ks, lane);
            ldb_frag(bl[0], sBl, wn,      ks, lane);
            ldb_frag(bl[1], sBl, wn + 16, ks, lane);
            #pragma unroll
            for (int mf = 0; mf < 4; mf++)
                #pragma unroll
                for (int nf = 0; nf < 4; nf++) {
                    MMA_BF16(acc[mf][nf], ah[mf], bh[nf>>1][(nf&1)*2], bh[nf>>1][(nf&1)*2+1]);
                    MMA_BF16(acc[mf][nf], ah[mf], bl[nf>>1][(nf&1)*2], bl[nf>>1][(nf&1)*2+1]);
                    MMA_BF16(acc[mf][nf], al[mf], bh[nf>>1][(nf&1)*2], bh[nf>>1][(nf&1)*2+1]);
                }
        }
    }

    const int g = lane >> 2, tq = lane & 3;
    #pragma unroll
    for (int mf = 0; mf < 4; mf++) {
        #pragma unroll
        for (int nf = 0; nf < 4; nf++) {
            long r0 = row0 + wm + mf*16 + g, r1 = r0 + 8;
            int  cb = col0 + wn + nf*8 + tq*2;
            float b0 = bias[cb], b1 = bias[cb + 1];
            float v00 = acc[mf][nf][0] + b0, v01 = acc[mf][nf][1] + b1;
            float v10 = acc[mf][nf][2] + b0, v11 = acc[mf][nf][3] + b1;
            if (mode == 2) {
                *reinterpret_cast<float2*>(OutF + r0 * DD + cb) = make_float2(v00, v01);
                *reinterpret_cast<float2*>(OutF + r1 * DD + cb) = make_float2(v10, v11);
            } else if (mode == 0) {
                unsigned short h0,h1,l0,l1;
                split2(v00,h0,l0); split2(v01,h1,l1);
                *reinterpret_cast<uint32_t*>(OutHi + r0*DD + cb) = (uint32_t)h0 | ((uint32_t)h1<<16);
                *reinterpret_cast<uint32_t*>(OutLo + r0*DD + cb) = (uint32_t)l0 | ((uint32_t)l1<<16);
                split2(v10,h0,l0); split2(v11,h1,l1);
                *reinterpret_cast<uint32_t*>(OutHi + r1*DD + cb) = (uint32_t)h0 | ((uint32_t)h1<<16);
                *reinterpret_cast<uint32_t*>(OutLo + r1*DD + cb) = (uint32_t)l0 | ((uint32_t)l1<<16);
            } else {
                #pragma unroll
                for (int e = 0; e < 4; e++) {
                    long rr = (e < 2) ? r0 : r1;
                    int  cc = cb + (e & 1);
                    float v = (e==0)?v00:(e==1)?v01:(e==2)?v10:v11;
                    unsigned short h, l; split2(v, h, l);
                    long f = rr * DD + cc;
                    long n = f >> 17, rem = f & 131071;
                    long kpos = rem >> 6, cdim = rem & 63;
                    long addr = n * 131072 + cdim * 2048 + kpos;
                    OutHi[addr] = __ushort_as_bfloat16(h);
                    OutLo[addr] = __ushort_as_bfloat16(l);
                }
            }
        }
    }
}

// ---------------------------------------------------------------------------
// Scores: per head, 128x128 tile, K=64 (2 chunks, both prefetched async).
// Epilogue: exp(s/8) -> attn, row partial sums.
// ---------------------------------------------------------------------------
#define SC_DSMEM (2*40960)
__global__ void __launch_bounds__(256) scores_mma_kernel(
    const __nv_bfloat16* __restrict__ Qhi, const __nv_bfloat16* __restrict__ Qlo,
    const __nv_bfloat16* __restrict__ Khi, const __nv_bfloat16* __restrict__ Klo,
    float* __restrict__ attn, float* __restrict__ part)
{
    extern __shared__ __align__(16) char smem[];
    __shared__ float srow[128][4];
    const uint32_t sb = smem_u32(smem);
    const int tid = threadIdx.x, wid = tid >> 5, lane = tid & 31;
    const int z = blockIdx.z;
    const int row0 = blockIdx.y * 128, col0 = blockIdx.x * 128;
    const int wm = (wid >> 2) * 64, wn = (wid & 3) * 32;
    const long hoff = (long)z * LL * DHH;

    float acc[4][4][4];
    #pragma unroll
    for (int i = 0; i < 4; i++)
        #pragma unroll
        for (int j = 0; j < 4; j++)
            #pragma unroll
            for (int q = 0; q < 4; q++) acc[i][j][q] = 0.f;

    // prefetch both K-chunks
    #pragma unroll
    for (int c = 0; c < 2; c++) {
        uint32_t s = sb + c * 40960;
        load32_async(Qhi + hoff + (long)row0 * 64 + c*32, 64, 128, s,         tid);
        load32_async(Qlo + hoff + (long)row0 * 64 + c*32, 64, 128, s + 10240, tid);
        load32_async(Khi + hoff + (long)col0 * 64 + c*32, 64, 128, s + 20480, tid);
        load32_async(Klo + hoff + (long)col0 * 64 + c*32, 64, 128, s + 30720, tid);
        CP_COMMIT();
    }

    #pragma unroll
    for (int c = 0; c < 2; c++) {
        if (c == 0) CP_WAIT1(); else CP_WAIT0();
        __syncthreads();
        uint32_t sc = sb + c * 40960;
        uint32_t sAh = sc, sAl = sc + 10240, sBh = sc + 20480, sBl = sc + 30720;
        #pragma unroll
        for (int ks = 0; ks < 32; ks += 16) {
            uint32_t ah[4][4], al[4][4], bh[2][4], bl[2][4];
            #pragma unroll
            for (int mf = 0; mf < 4; mf++) {
                lda_frag(ah[mf], sAh, wm + mf*16, ks, lane);
                lda_frag(al[mf], sAl, wm + mf*16, ks, lane);
            }
            ldb_frag(bh[0], sBh, wn,      ks, lane);
            ldb_frag(bh[1], sBh, wn + 16, ks, lane);
            ldb_frag(bl[0], sBl, wn,      ks, lane);
            ldb_frag(bl[1], sBl, wn + 16, ks, lane);
            #pragma unroll
            for (int mf = 0; mf < 4; mf++)
                #pragma unroll
                for (int nf = 0; nf < 4; nf++) {
                    MMA_BF16(acc[mf][nf], ah[mf], bh[nf>>1][(nf&1)*2], bh[nf>>1][(nf&1)*2+1]);
                    MMA_BF16(acc[mf][nf], ah[mf], bl[nf>>1][(nf&1)*2], bl[nf>>1][(nf&1)*2+1]);
                    MMA_BF16(acc[mf][nf], al[mf], bh[nf>>1][(nf&1)*2], bh[nf>>1][(nf&1)*2+1]);
                }
        }
    }

    const int g = lane >> 2, tq = lane & 3;
    float* ap = attn + (long)z * LL * LL;
    #pragma unroll
    for (int mf = 0; mf < 4; mf++) {
        float s0 = 0.f, s1 = 0.f;
        long r0 = row0 + wm + mf*16 + g, r1 = r0 + 8;
        #pragma unroll
        for (int nf = 0; nf < 4; nf++) {
            int cb = col0 + wn + nf*8 + tq*2;
            float e00 = __expf(acc[mf][nf][0] * 0.125f);
            float e01 = __expf(acc[mf][nf][1] * 0.125f);
            float e10 = __expf(acc[mf][nf][2] * 0.125f);
            float e11 = __expf(acc[mf][nf][3] * 0.125f);
            s0 += e00 + e01; s1 += e10 + e11;
            *reinterpret_cast<float2*>(ap + r0 * LL + cb) = make_float2(e00, e01);
            *reinterpret_cast<float2*>(ap + r1 * LL + cb) = make_float2(e10, e11);
        }
        s0 += __shfl_xor_sync(0xffffffffu, s0, 1);
        s0 += __shfl_xor_sync(0xffffffffu, s0, 2);
        s1 += __shfl_xor_sync(0xffffffffu, s1, 1);
        s1 += __shfl_xor_sync(0xffffffffu, s1, 2);
        if (tq == 0) {
            srow[wm + mf*16 + g][wid & 3]     = s0;
            srow[wm + mf*16 + g + 8][wid & 3] = s1;
        }
    }
    __syncthreads();
    if (tid < 128) {
        float t = srow[tid][0] + srow[tid][1] + srow[tid][2] + srow[tid][3];
        part[((long)z * LL + row0 + tid) * 16 + blockIdx.x] = t;
    }
}

// ---------------------------------------------------------------------------
// Row reciprocal
// ---------------------------------------------------------------------------
__global__ void __launch_bounds__(256) rowinv_kernel(const float* __restrict__ part,
                                                     float* __restrict__ rinv) {
    long i = (long)blockIdx.x * 256 + threadIdx.x;
    float s = 0.f;
    #pragma unroll
    for (int t = 0; t < 16; t++) s += part[i * 16 + t];
    rinv[i] = 1.0f / s;
}

// ---------------------------------------------------------------------------
// AV, cp.async staged: normalize attn chunk (smem-staged), write back, split,
// MMA vs Vt. Block 128x64. Dyn smem: Ah(10240) Al(10240),
// stages at 20480 + s*26624: ATTN f32(16384) Vh(5120) Vl(5120)
// ---------------------------------------------------------------------------
#define AV_DSMEM (20480 + 2*26624)
__global__ void __launch_bounds__(256) av_mma_kernel(
    float* __restrict__ attn,
    const __nv_bfloat16* __restrict__ Vthi, const __nv_bfloat16* __restrict__ Vtlo,
    const float* __restrict__ rinv,
    __nv_bfloat16* __restrict__ CtxHi, __nv_bfloat16* __restrict__ CtxLo)
{
    extern __shared__ __align__(16) char smem[];
    __shared__ float rvs[128];
    const uint32_t sb = smem_u32(smem);
    const int tid = threadIdx.x, wid = tid >> 5, lane = tid & 31;
    const int z = blockIdx.y;
    const int row0 = blockIdx.x * 128;
    const int wm = (wid >> 2) * 64, wn = (wid & 3) * 16;

    float* ab = attn + (long)z * LL * LL + (long)row0 * LL;
    const __nv_bfloat16* vh = Vthi + (long)z * LL * DHH;
    const __nv_bfloat16* vl = Vtlo + (long)z * LL * DHH;

    if (tid < 128) rvs[tid] = rinv[(long)z * LL + row0 + tid];

    float acc[4][2][4];
    #pragma unroll
    for (int i = 0; i < 4; i++)
        #pragma unroll
        for (int j = 0; j < 2; j++)
            #pragma unroll
            for (int q = 0; q < 4; q++) acc[i][j][q] = 0.f;

    const uint32_t AH = sb, AL = sb + 10240;

    // prologue stage 0
    {
        uint32_t s0 = sb + 20480;
        for (int i = tid; i < 1024; i += 256) {          // 128 rows x 8 x 16B
            int row = i >> 3, q = i & 7;
            cp16(s0 + row * 128 + q * 16, ab + (long)row * LL + q * 4);
        }
        load32_async(vh, LL, 64, s0 + 16384, tid);
        load32_async(vl, LL, 64, s0 + 21504, tid);
        CP_COMMIT();
    }

    const int NC = LL / 32;   // 64
    for (int c = 0; c < NC; c++) {
        CP_WAIT0();
        __syncthreads();
        if (c + 1 < NC) {
            uint32_t sn = sb + 20480 + ((c + 1) & 1) * 26624;
            long goff = (long)(c + 1) * 32;
            for (int i = tid; i < 1024; i += 256) {
                int row = i >> 3, q = i & 7;
                cp16(sn + row * 128 + q * 16, ab + (long)row * LL + goff + q * 4);
            }
            load32_async(vh + goff, LL, 64, sn + 16384, tid);
            load32_async(vl + goff, LL, 64, sn + 21504, tid);
            CP_COMMIT();
        }
        uint32_t sc = sb + 20480 + (c & 1) * 26624;
        char* stg = smem + (sc - sb);

        // normalize from staging, write back to global, split into A tiles
        for (int i = tid; i < 1024; i += 256) {
            int row = i >> 3, q = i & 7;
            float4 v = *reinterpret_cast<const float4*>(stg + row * 128 + q * 16);
            float r = rvs[row];
            v.x *= r; v.y *= r; v.z *= r; v.w *= r;
            *reinterpret_cast<float4*>(ab + (long)row * LL + (long)c * 32 + q * 4) = v;
            unsigned short h0,h1,h2,h3,l0,l1,l2,l3;
            split2(v.x,h0,l0); split2(v.y,h1,l1); split2(v.z,h2,l2); split2(v.w,h3,l3);
            uint2 uh, ul;
            uh.x = (uint32_t)h0 | ((uint32_t)h1 << 16);
            uh.y = (uint32_t)h2 | ((uint32_t)h3 << 16);
            ul.x = (uint32_t)l0 | ((uint32_t)l1 << 16);
            ul.y = (uint32_t)l2 | ((uint32_t)l3 << 16);
            *reinterpret_cast<uint2*>(smem + row * 80 + q * 8)         = uh;
            *reinterpret_cast<uint2*>(smem + 10240 + row * 80 + q * 8) = ul;
        }
        __syncthreads();

        uint32_t sBh = sc + 16384, sBl = sc + 21504;
        #pragma unroll
        for (int ks = 0; ks < 32; ks += 16) {
            uint32_t ah[4][4], al[4][4], bh[4], bl[4];
            #pragma unroll
            for (int mf = 0; mf < 4; mf++) {
                lda_frag(ah[mf], AH, wm + mf*16, ks, lane);
                lda_frag(al[mf], AL, wm + mf*16, ks, lane);
            }
            ldb_frag(bh, sBh, wn, ks, lane);
            ldb_frag(bl, sBl, wn, ks, lane);
            #pragma unroll
            for (int mf = 0; mf < 4; mf++)
                #pragma unroll
                for (int nf = 0; nf < 2; nf++) {
                    MMA_BF16(acc[mf][nf], ah[mf], bh[nf*2], bh[nf*2+1]);
                    MMA_BF16(acc[mf][nf], ah[mf], bl[nf*2], bl[nf*2+1]);
                    MMA_BF16(acc[mf][nf], al[mf], bh[nf*2], bh[nf*2+1]);
                }
        }
    }

    const int g = lane >> 2, tq = lane & 3;
    #pragma unroll
    for (int mf = 0; mf < 4; mf++)
        #pragma unroll
        for (int nf = 0; nf < 2; nf++) {
            long r0 = row0 + wm + mf*16 + g, r1 = r0 + 8;
            int cb = wn + nf*8 + tq*2;
            unsigned short h0,h1,l0,l1;
            long o0 = (long)z * LL * DHH + r0 * 64 + cb;
            long o1 = (long)z * LL * DHH + r1 * 64 + cb;
            split2(acc[mf][nf][0], h0, l0); split2(acc[mf][nf][1], h1, l1);
            *reinterpret_cast<uint32_t*>(CtxHi + o0) = (uint32_t)h0 | ((uint32_t)h1<<16);
            *reinterpret_cast<uint32_t*>(CtxLo + o0) = (uint32_t)l0 | ((uint32_t)l1<<16);
            split2(acc[mf][nf][2], h0, l0); split2(acc[mf][nf][3], h1, l1);
            *reinterpret_cast<uint32_t*>(CtxHi + o1) = (uint32_t)h0 | ((uint32_t)h1<<16);
            *reinterpret_cast<uint32_t*>(CtxLo + o1) = (uint32_t)l0 | ((uint32_t)l1<<16);
        }
}

// ---------------------------------------------------------------------------
// Residual + LayerNorm
// ---------------------------------------------------------------------------
__device__ __forceinline__ float warp_sum(float v) {
    #pragma unroll
    for (int o = 16; o > 0; o >>= 1) v += __shfl_xor_sync(0xffffffffu, v, o);
    return v;
}

__global__ void __launch_bounds__(256) ln_kernel(
    const float* __restrict__ proj, const float* __restrict__ resid,
    const float* __restrict__ gamma, const float* __restrict__ beta,
    float* __restrict__ out)
{
    const long row = blockIdx.x;
    const int tid = threadIdx.x, lane = tid & 31, wid = tid >> 5;
    __shared__ float red[8];

    float4 x = reinterpret_cast<const float4*>(proj + row * DD)[tid];
    float4 r = reinterpret_cast<const float4*>(resid + row * DD)[tid];
    x.x += r.x; x.y += r.y; x.z += r.z; x.w += r.w;

    float s = warp_sum(x.x + x.y + x.z + x.w);
    if (lane == 0) red[wid] = s;
    __syncthreads();
    if (wid == 0) {
        float t = (lane < 8) ? red[lane] : 0.f;
        t = warp_sum(t);
        if (lane == 0) red[0] = t;
    }
    __syncthreads();
    const float mu = red[0] * (1.0f / DD);
    __syncthreads();

    float dx = x.x - mu, dy = x.y - mu, dz = x.z - mu, dw = x.w - mu;
    float ss = warp_sum(dx*dx + dy*dy + dz*dz + dw*dw);
    if (lane == 0) red[wid] = ss;
    __syncthreads();
    if (wid == 0) {
        float t = (lane < 8) ? red[lane] : 0.f;
        t = warp_sum(t);
        if (lane == 0) red[0] = t;
    }
    __syncthreads();
    const float rs = rsqrtf(red[0] * (1.0f / DD) + LN_EPS);

    float4 gm = reinterpret_cast<const float4*>(gamma)[tid];
    float4 be = reinterpret_cast<const float4*>(beta)[tid];
    float4 o;
    o.x = dx * rs * gm.x + be.x;
    o.y = dy * rs * gm.y + be.y;
    o.z = dz * rs * gm.z + be.z;
    o.w = dw * rs * gm.w + be.w;
    reinterpret_cast<float4*>(out + row * DD)[tid] = o;
}

// ---------------------------------------------------------------------------
// Launch
// ---------------------------------------------------------------------------
extern "C" void kernel_launch(void* const* d_in, const int* in_sizes, int n_in,
                              void* d_out, int out_size)
{
    const float* query = (const float*)d_in[0];
    const float* key   = (const float*)d_in[1];
    const float* value = (const float*)d_in[2];
    const float* Wq = (const float*)d_in[3];
    const float* bq = (const float*)d_in[4];
    const float* Wk = (const float*)d_in[5];
    const float* bk = (const float*)d_in[6];
    const float* Wv = (const float*)d_in[7];
    const float* bv = (const float*)d_in[8];
    const float* Wo = (const float*)d_in[9];
    const float* bo = (const float*)d_in[10];
    const float* gamma = (const float*)d_in[11];
    const float* beta  = (const float*)d_in[12];

    float* out  = (float*)d_out;
    float* attn = out + OUT_ELEMS;

    __nv_bfloat16 *xqh,*xql,*xkh,*xkl,*xvh,*xvl;
    __nv_bfloat16 *wqh,*wql,*wkh,*wkl,*wvh,*wvl,*woh,*wol;
    __nv_bfloat16 *Qh,*Ql,*Kh,*Kl,*Vth,*Vtl,*ch,*cl;
    float *part,*rinv,*proj;
    cudaGetSymbolAddress((void**)&xqh, g_xq_h); cudaGetSymbolAddress((void**)&xql, g_xq_l);
    cudaGetSymbolAddress((void**)&xkh, g_xk_h); cudaGetSymbolAddress((void**)&xkl, g_xk_l);
    cudaGetSymbolAddress((void**)&xvh, g_xv_h); cudaGetSymbolAddress((void**)&xvl, g_xv_l);
    cudaGetSymbolAddress((void**)&wqh, g_wq_h); cudaGetSymbolAddress((void**)&wql, g_wq_l);
    cudaGetSymbolAddress((void**)&wkh, g_wk_h); cudaGetSymbolAddress((void**)&wkl, g_wk_l);
    cudaGetSymbolAddress((void**)&wvh, g_wv_h); cudaGetSymbolAddress((void**)&wvl, g_wv_l);
    cudaGetSymbolAddress((void**)&woh, g_wo_h); cudaGetSymbolAddress((void**)&wol, g_wo_l);
    cudaGetSymbolAddress((void**)&Qh,  g_Qh);   cudaGetSymbolAddress((void**)&Ql,  g_Ql);
    cudaGetSymbolAddress((void**)&Kh,  g_Kh);   cudaGetSymbolAddress((void**)&Kl,  g_Kl);
    cudaGetSymbolAddress((void**)&Vth, g_Vth);  cudaGetSymbolAddress((void**)&Vtl, g_Vtl);
    cudaGetSymbolAddress((void**)&ch,  g_ctxh); cudaGetSymbolAddress((void**)&cl,  g_ctxl);
    cudaGetSymbolAddress((void**)&part, g_part);
    cudaGetSymbolAddress((void**)&rinv, g_rinv);
    cudaGetSymbolAddress((void**)&proj, g_proj);

    cudaFuncSetAttribute(proj_mma_kernel,   cudaFuncAttributeMaxDynamicSharedMemorySize, PROJ_DSMEM);
    cudaFuncSetAttribute(scores_mma_kernel, cudaFuncAttributeMaxDynamicSharedMemorySize, SC_DSMEM);
    cudaFuncSetAttribute(av_mma_kernel,     cudaFuncAttributeMaxDynamicSharedMemorySize, AV_DSMEM);

    // 1) fp32 -> split bf16
    split_kernel<<<OUT_ELEMS/1024, 256>>>(query, xqh, xql);
    split_kernel<<<OUT_ELEMS/1024, 256>>>(key,   xkh, xkl);
    split_kernel<<<OUT_ELEMS/1024, 256>>>(value, xvh, xvl);
    split_kernel<<<DD*DD/1024, 256>>>(Wq, wqh, wql);
    split_kernel<<<DD*DD/1024, 256>>>(Wk, wkh, wkl);
    split_kernel<<<DD*DD/1024, 256>>>(Wv, wvh, wvl);
    split_kernel<<<DD*DD/1024, 256>>>(Wo, woh, wol);

    // 2) Projections
    dim3 gp(DD/128, MROWS/128);
    proj_mma_kernel<<<gp, 256, PROJ_DSMEM>>>(xqh, xql, wqh, wql, bq, Qh, Ql, nullptr, 0);
    proj_mma_kernel<<<gp, 256, PROJ_DSMEM>>>(xkh, xkl, wkh, wkl, bk, Kh, Kl, nullptr, 0);
    proj_mma_kernel<<<gp, 256, PROJ_DSMEM>>>(xvh, xvl, wvh, wvl, bv, Vth, Vtl, nullptr, 1);

    // 3) Scores + exp + partial sums
    dim3 gs(LL/128, LL/128, BH);
    scores_mma_kernel<<<gs, 256, SC_DSMEM>>>(Qh, Ql, Kh, Kl, attn, part);

    // 4) Row reciprocals
    rowinv_kernel<<<(BH*LL)/256, 256>>>(part, rinv);

    // 5) AV (normalizes attention in place, writes ctx hi/lo)
    dim3 ga(LL/128, BH);
    av_mma_kernel<<<ga, 256, AV_DSMEM>>>(attn, Vth, Vtl, rinv, ch, cl);

    // 6) Out projection + residual + LN
    proj_mma_kernel<<<gp, 256, PROJ_DSMEM>>>(ch, cl, woh, wol, bo, nullptr, nullptr, proj, 2);
    ln_kernel<<<MROWS, 256>>>(proj, query, gamma, beta, out);
}

// round 9
// speedup vs baseline: 2.6949x; 1.0232x over previous
#include <cuda_runtime.h>
#include <cuda_bf16.h>
#include <cstdint>

#define BB 2
#define LL 2048
#define DD 1024
#define HH 16
#define DHH 64
#define BH (BB*HH)
#define MROWS (BB*LL)           // 4096
#define OUT_ELEMS (MROWS*DD)
#define LN_EPS 1e-5f

// ---------------------------------------------------------------------------
// Static device scratch
// ---------------------------------------------------------------------------
__device__ __nv_bfloat16 g_xq_h[MROWS*DD], g_xq_l[MROWS*DD];
__device__ __nv_bfloat16 g_xk_h[MROWS*DD], g_xk_l[MROWS*DD];
__device__ __nv_bfloat16 g_xv_h[MROWS*DD], g_xv_l[MROWS*DD];
__device__ __nv_bfloat16 g_wq_h[DD*DD], g_wq_l[DD*DD];
__device__ __nv_bfloat16 g_wk_h[DD*DD], g_wk_l[DD*DD];
__device__ __nv_bfloat16 g_wv_h[DD*DD], g_wv_l[DD*DD];
__device__ __nv_bfloat16 g_wo_h[DD*DD], g_wo_l[DD*DD];
__device__ __nv_bfloat16 g_Qh[MROWS*DD], g_Ql[MROWS*DD];
__device__ __nv_bfloat16 g_Kh[MROWS*DD], g_Kl[MROWS*DD];
__device__ __nv_bfloat16 g_Vth[MROWS*DD], g_Vtl[MROWS*DD];  // [n][c][k]
__device__ __nv_bfloat16 g_ctxh[MROWS*DD], g_ctxl[MROWS*DD];
__device__ float g_part[(long)BH*LL*16];
__device__ float g_rinv[(long)BH*LL];
__device__ float g_proj[MROWS*DD];

// ---------------------------------------------------------------------------
// PTX helpers
// ---------------------------------------------------------------------------
__device__ __forceinline__ uint32_t smem_u32(const void* p) {
    uint32_t a;
    asm("{ .reg .u64 t; cvta.to.shared.u64 t, %1; cvt.u32.u64 %0, t; }" : "=r"(a) : "l"(p));
    return a;
}

#define LDMX4(r0,r1,r2,r3,addr) \
    asm volatile("ldmatrix.sync.aligned.m8n8.x4.shared.b16 {%0,%1,%2,%3}, [%4];" \
        : "=r"(r0), "=r"(r1), "=r"(r2), "=r"(r3) : "r"(addr))

#define MMA_BF16(d, a, b0v, b1v) \
    asm volatile("mma.sync.aligned.m16n8k16.row.col.f32.bf16.bf16.f32 " \
        "{%0,%1,%2,%3},{%4,%5,%6,%7},{%8,%9},{%0,%1,%2,%3};" \
        : "+f"((d)[0]), "+f"((d)[1]), "+f"((d)[2]), "+f"((d)[3]) \
        : "r"((a)[0]), "r"((a)[1]), "r"((a)[2]), "r"((a)[3]), "r"(b0v), "r"(b1v))

__device__ __forceinline__ void cp16(uint32_t dst, const void* src) {
    asm volatile("cp.async.cg.shared.global [%0], [%1], 16;" :: "r"(dst), "l"(src));
}
#define CP_COMMIT() asm volatile("cp.async.commit_group;" ::: "memory")
#define CP_WAIT0()  asm volatile("cp.async.wait_group 0;" ::: "memory")
#define CP_WAIT1()  asm volatile("cp.async.wait_group 1;" ::: "memory")

__device__ __forceinline__ void lda_frag(uint32_t a[4], uint32_t base, int mbase, int ks, int lane) {
    int row = mbase + (lane & 7) + ((lane >> 3) & 1) * 8;
    int col = ks + (lane >> 4) * 8;
    LDMX4(a[0], a[1], a[2], a[3], base + row * 80 + col * 2);
}
__device__ __forceinline__ void ldb_frag(uint32_t b[4], uint32_t base, int nbase, int ks, int lane) {
    int r = lane & 7, gp = lane >> 3;
    int n = nbase + (gp >> 1) * 8 + r;
    int col = ks + (gp & 1) * 8;
    LDMX4(b[0], b[1], b[2], b[3], base + n * 80 + col * 2);
}

__device__ __forceinline__ void load32_async(const __nv_bfloat16* __restrict__ src, long ld,
                                             int R, uint32_t base, int tid) {
    for (int i = tid; i < R * 4; i += 256) {
        int row = i >> 2, q = i & 3;
        cp16(base + row * 80 + q * 16, src + (long)row * ld + q * 8);
    }
}

__device__ __forceinline__ void split2(float v, unsigned short& h, unsigned short& l) {
    __nv_bfloat16 bh = __float2bfloat16(v);
    __nv_bfloat16 bl = __float2bfloat16(v - __bfloat162float(bh));
    h = __bfloat16_as_ushort(bh); l = __bfloat16_as_ushort(bl);
}

// ---------------------------------------------------------------------------
// fp32 -> (hi,lo) split; merged launches via blockIdx.y source select
// ---------------------------------------------------------------------------
__global__ void __launch_bounds__(256) split_inputs_kernel(
    const float* __restrict__ s0, const float* __restrict__ s1, const float* __restrict__ s2)
{
    const int which = blockIdx.y;
    const float* src = which == 0 ? s0 : which == 1 ? s1 : s2;
    __nv_bfloat16* hi = which == 0 ? g_xq_h : which == 1 ? g_xk_h : g_xv_h;
    __nv_bfloat16* lo = which == 0 ? g_xq_l : which == 1 ? g_xk_l : g_xv_l;
    long i = (long)blockIdx.x * 256 + threadIdx.x;
    float4 v = reinterpret_cast<const float4*>(src)[i];
    unsigned short h0,h1,h2,h3,l0,l1,l2,l3;
    split2(v.x,h0,l0); split2(v.y,h1,l1); split2(v.z,h2,l2); split2(v.w,h3,l3);
    uint2 uh, ul;
    uh.x = (uint32_t)h0 | ((uint32_t)h1 << 16); uh.y = (uint32_t)h2 | ((uint32_t)h3 << 16);
    ul.x = (uint32_t)l0 | ((uint32_t)l1 << 16); ul.y = (uint32_t)l2 | ((uint32_t)l3 << 16);
    reinterpret_cast<uint2*>(hi)[i] = uh;
    reinterpret_cast<uint2*>(lo)[i] = ul;
}

__global__ void __launch_bounds__(256) split_weights_kernel(
    const float* __restrict__ s0, const float* __restrict__ s1,
    const float* __restrict__ s2, const float* __restrict__ s3)
{
    const int which = blockIdx.y;
    const float* src = which == 0 ? s0 : which == 1 ? s1 : which == 2 ? s2 : s3;
    __nv_bfloat16* hi = which == 0 ? g_wq_h : which == 1 ? g_wk_h : which == 2 ? g_wv_h : g_wo_h;
    __nv_bfloat16* lo = which == 0 ? g_wq_l : which == 1 ? g_wk_l : which == 2 ? g_wv_l : g_wo_l;
    long i = (long)blockIdx.x * 256 + threadIdx.x;
    float4 v = reinterpret_cast<const float4*>(src)[i];
    unsigned short h0,h1,h2,h3,l0,l1,l2,l3;
    split2(v.x,h0,l0); split2(v.y,h1,l1); split2(v.z,h2,l2); split2(v.w,h3,l3);
    uint2 uh, ul;
    uh.x = (uint32_t)h0 | ((uint32_t)h1 << 16); uh.y = (uint32_t)h2 | ((uint32_t)h3 << 16);
    ul.x = (uint32_t)l0 | ((uint32_t)l1 << 16); ul.y = (uint32_t)l2 | ((uint32_t)l3 << 16);
    reinterpret_cast<uint2*>(hi)[i] = uh;
    reinterpret_cast<uint2*>(lo)[i] = ul;
}

// ---------------------------------------------------------------------------
// Shared 3-stage-pipelined GEMM mainloop (block 128x128, BK=32, K=1024)
// Stage layout (40960B): Ah(10240) Al Bh Bl
// ---------------------------------------------------------------------------
#define PROJ_DSMEM (3*40960)
__device__ __forceinline__ void proj_mainloop(
    const __nv_bfloat16* __restrict__ Ah_, const __nv_bfloat16* __restrict__ Al_,
    const __nv_bfloat16* __restrict__ Bh_, const __nv_bfloat16* __restrict__ Bl_,
    uint32_t sb, int tid, int lane, int wm, int wn, float acc[4][4][4])
{
    const int NC = DD / 32;   // 32
    // prologue: stages 0,1
    #pragma unroll
    for (int p = 0; p < 2; p++) {
        uint32_t s = sb + p * 40960;
        load32_async(Ah_ + p*32, DD, 128, s,         tid);
        load32_async(Al_ + p*32, DD, 128, s + 10240, tid);
        load32_async(Bh_ + p*32, DD, 128, s + 20480, tid);
        load32_async(Bl_ + p*32, DD, 128, s + 30720, tid);
        CP_COMMIT();
    }
    for (int c = 0; c < NC; c++) {
        CP_WAIT1();
        __syncthreads();
        if (c + 2 < NC) {
            uint32_t sn = sb + ((c + 2) % 3) * 40960;
            load32_async(Ah_ + (c+2)*32, DD, 128, sn,         tid);
            load32_async(Al_ + (c+2)*32, DD, 128, sn + 10240, tid);
            load32_async(Bh_ + (c+2)*32, DD, 128, sn + 20480, tid);
            load32_async(Bl_ + (c+2)*32, DD, 128, sn + 30720, tid);
            CP_COMMIT();
        } else {
            CP_COMMIT();   // keep group accounting uniform
        }
        uint32_t sc = sb + (c % 3) * 40960;
        uint32_t sAh = sc, sAl = sc + 10240, sBh = sc + 20480, sBl = sc + 30720;
        #pragma unroll
        for (int ks = 0; ks < 32; ks += 16) {
            uint32_t ah[4][4], al[4][4], bh[2][4], bl[2][4];
            #pragma unroll
            for (int mf = 0; mf < 4; mf++) {
                lda_frag(ah[mf], sAh, wm + mf*16, ks, lane);
                lda_frag(al[mf], sAl, wm + mf*16, ks, lane);
            }
            ldb_frag(bh[0], sBh, wn,      ks, lane);
            ldb_frag(bh[1], sBh, wn + 16, ks, lane);
            ldb_frag(bl[0], sBl, wn,      ks, lane);
            ldb_frag(bl[1], sBl, wn + 16, ks, lane);
            #pragma unroll
            for (int mf = 0; mf < 4; mf++)
                #pragma unroll
                for (int nf = 0; nf < 4; nf++) {
                    MMA_BF16(acc[mf][nf], ah[mf], bh[nf>>1][(nf&1)*2], bh[nf>>1][(nf&1)*2+1]);
                    MMA_BF16(acc[mf][nf], ah[mf], bl[nf>>1][(nf&1)*2], bl[nf>>1][(nf&1)*2+1]);
                    MMA_BF16(acc[mf][nf], al[mf], bh[nf>>1][(nf&1)*2], bh[nf>>1][(nf&1)*2+1]);
                }
        }
    }
}

// ---------------------------------------------------------------------------
// Fused Q/K/V projection: grid (8, 32, 3). z selects operands from globals.
// z=0: Q (flat hi/lo), z=1: K (flat hi/lo), z=2: V (Vt scatter)
// ---------------------------------------------------------------------------
__global__ void __launch_bounds__(256) qkv_proj_kernel(
    const float* __restrict__ bq, const float* __restrict__ bk, const float* __restrict__ bv)
{
    extern __shared__ __align__(16) char smem[];
    const uint32_t sb = smem_u32(smem);
    const int tid = threadIdx.x, wid = tid >> 5, lane = tid & 31;
    const int row0 = blockIdx.y * 128, col0 = blockIdx.x * 128;
    const int wm = (wid >> 2) * 64, wn = (wid & 3) * 32;
    const int z = blockIdx.z;

    const __nv_bfloat16* Ah_ = (z == 0 ? g_xq_h : z == 1 ? g_xk_h : g_xv_h) + (long)row0 * DD;
    const __nv_bfloat16* Al_ = (z == 0 ? g_xq_l : z == 1 ? g_xk_l : g_xv_l) + (long)row0 * DD;
    const __nv_bfloat16* Bh_ = (z == 0 ? g_wq_h : z == 1 ? g_wk_h : g_wv_h) + (long)col0 * DD;
    const __nv_bfloat16* Bl_ = (z == 0 ? g_wq_l : z == 1 ? g_wk_l : g_wv_l) + (long)col0 * DD;
    const float* bias = z == 0 ? bq : z == 1 ? bk : bv;

    float acc[4][4][4];
    #pragma unroll
    for (int i = 0; i < 4; i++)
        #pragma unroll
        for (int j = 0; j < 4; j++)
            #pragma unroll
            for (int q = 0; q < 4; q++) acc[i][j][q] = 0.f;

    proj_mainloop(Ah_, Al_, Bh_, Bl_, sb, tid, lane, wm, wn, acc);

    const int g = lane >> 2, tq = lane & 3;
    __nv_bfloat16* OutHi = z == 0 ? g_Qh : g_Kh;
    __nv_bfloat16* OutLo = z == 0 ? g_Ql : g_Kl;
    #pragma unroll
    for (int mf = 0; mf < 4; mf++) {
        #pragma unroll
        for (int nf = 0; nf < 4; nf++) {
            long r0 = row0 + wm + mf*16 + g, r1 = r0 + 8;
            int  cb = col0 + wn + nf*8 + tq*2;
            float b0 = bias[cb], b1 = bias[cb + 1];
            float v00 = acc[mf][nf][0] + b0, v01 = acc[mf][nf][1] + b1;
            float v10 = acc[mf][nf][2] + b0, v11 = acc[mf][nf][3] + b1;
            if (z < 2) {
                unsigned short h0,h1,l0,l1;
                split2(v00,h0,l0); split2(v01,h1,l1);
                *reinterpret_cast<uint32_t*>(OutHi + r0*DD + cb) = (uint32_t)h0 | ((uint32_t)h1<<16);
                *reinterpret_cast<uint32_t*>(OutLo + r0*DD + cb) = (uint32_t)l0 | ((uint32_t)l1<<16);
                split2(v10,h0,l0); split2(v11,h1,l1);
                *reinterpret_cast<uint32_t*>(OutHi + r1*DD + cb) = (uint32_t)h0 | ((uint32_t)h1<<16);
                *reinterpret_cast<uint32_t*>(OutLo + r1*DD + cb) = (uint32_t)l0 | ((uint32_t)l1<<16);
            } else {
                #pragma unroll
                for (int e = 0; e < 4; e++) {
                    long rr = (e < 2) ? r0 : r1;
                    int  cc = cb + (e & 1);
                    float v = (e==0)?v00:(e==1)?v01:(e==2)?v10:v11;
                    unsigned short h, l; split2(v, h, l);
                    long f = rr * DD + cc;
                    long n = f >> 17, rem = f & 131071;
                    long kpos = rem >> 6, cdim = rem & 63;
                    long addr = n * 131072 + cdim * 2048 + kpos;
                    g_Vth[addr] = __ushort_as_bfloat16(h);
                    g_Vtl[addr] = __ushort_as_bfloat16(l);
                }
            }
        }
    }
}

// ---------------------------------------------------------------------------
// Output projection (fp32 result)
// ---------------------------------------------------------------------------
__global__ void __launch_bounds__(256) outproj_kernel(const float* __restrict__ bo)
{
    extern __shared__ __align__(16) char smem[];
    const uint32_t sb = smem_u32(smem);
    const int tid = threadIdx.x, wid = tid >> 5, lane = tid & 31;
    const int row0 = blockIdx.y * 128, col0 = blockIdx.x * 128;
    const int wm = (wid >> 2) * 64, wn = (wid & 3) * 32;

    float acc[4][4][4];
    #pragma unroll
    for (int i = 0; i < 4; i++)
        #pragma unroll
        for (int j = 0; j < 4; j++)
            #pragma unroll
            for (int q = 0; q < 4; q++) acc[i][j][q] = 0.f;

    proj_mainloop(g_ctxh + (long)row0 * DD, g_ctxl + (long)row0 * DD,
                  g_wo_h + (long)col0 * DD, g_wo_l + (long)col0 * DD,
                  sb, tid, lane, wm, wn, acc);

    const int g = lane >> 2, tq = lane & 3;
    #pragma unroll
    for (int mf = 0; mf < 4; mf++)
        #pragma unroll
        for (int nf = 0; nf < 4; nf++) {
            long r0 = row0 + wm + mf*16 + g, r1 = r0 + 8;
            int  cb = col0 + wn + nf*8 + tq*2;
            float b0 = bo[cb], b1 = bo[cb + 1];
            *reinterpret_cast<float2*>(g_proj + r0 * DD + cb) =
                make_float2(acc[mf][nf][0] + b0, acc[mf][nf][1] + b1);
            *reinterpret_cast<float2*>(g_proj + r1 * DD + cb) =
                make_float2(acc[mf][nf][2] + b0, acc[mf][nf][3] + b1);
        }
}

// ---------------------------------------------------------------------------
// Scores: 128x128 tile per head, K=64 (both chunks prefetched).
// Epilogue: exp(s/8) staged in smem, coalesced 128B row writes + row partials.
// ---------------------------------------------------------------------------
#define SC_DSMEM (2*40960)
__global__ void __launch_bounds__(256) scores_mma_kernel(
    float* __restrict__ attn, float* __restrict__ part)
{
    extern __shared__ __align__(16) char smem[];
    __shared__ float srow[128][4];
    const uint32_t sb = smem_u32(smem);
    const int tid = threadIdx.x, wid = tid >> 5, lane = tid & 31;
    const int z = blockIdx.z;
    const int row0 = blockIdx.y * 128, col0 = blockIdx.x * 128;
    const int wm = (wid >> 2) * 64, wn = (wid & 3) * 32;
    const long hoff = (long)z * LL * DHH;

    float acc[4][4][4];
    #pragma unroll
    for (int i = 0; i < 4; i++)
        #pragma unroll
        for (int j = 0; j < 4; j++)
            #pragma unroll
            for (int q = 0; q < 4; q++) acc[i][j][q] = 0.f;

    #pragma unroll
    for (int c = 0; c < 2; c++) {
        uint32_t s = sb + c * 40960;
        load32_async(g_Qh + hoff + (long)row0 * 64 + c*32, 64, 128, s,         tid);
        load32_async(g_Ql + hoff + (long)row0 * 64 + c*32, 64, 128, s + 10240, tid);
        load32_async(g_Kh + hoff + (long)col0 * 64 + c*32, 64, 128, s + 20480, tid);
        load32_async(g_Kl + hoff + (long)col0 * 64 + c*32, 64, 128, s + 30720, tid);
        CP_COMMIT();
    }

    #pragma unroll
    for (int c = 0; c < 2; c++) {
        if (c == 0) CP_WAIT1(); else CP_WAIT0();
        __syncthreads();
        uint32_t sc = sb + c * 40960;
        uint32_t sAh = sc, sAl = sc + 10240, sBh = sc + 20480, sBl = sc + 30720;
        #pragma unroll
        for (int ks = 0; ks < 32; ks += 16) {
            uint32_t ah[4][4], al[4][4], bh[2][4], bl[2][4];
            #pragma unroll
            for (int mf = 0; mf < 4; mf++) {
                lda_frag(ah[mf], sAh, wm + mf*16, ks, lane);
                lda_frag(al[mf], sAl, wm + mf*16, ks, lane);
            }
            ldb_frag(bh[0], sBh, wn,      ks, lane);
            ldb_frag(bh[1], sBh, wn + 16, ks, lane);
            ldb_frag(bl[0], sBl, wn,      ks, lane);
            ldb_frag(bl[1], sBl, wn + 16, ks, lane);
            #pragma unroll
            for (int mf = 0; mf < 4; mf++)
                #pragma unroll
                for (int nf = 0; nf < 4; nf++) {
                    MMA_BF16(acc[mf][nf], ah[mf], bh[nf>>1][(nf&1)*2], bh[nf>>1][(nf&1)*2+1]);
                    MMA_BF16(acc[mf][nf], ah[mf], bl[nf>>1][(nf&1)*2], bl[nf>>1][(nf&1)*2+1]);
                    MMA_BF16(acc[mf][nf], al[mf], bh[nf>>1][(nf&1)*2], bh[nf>>1][(nf&1)*2+1]);
                }
        }
    }

    // epilogue: exp -> smem staging (row stride 132 f32), row partials
    __syncthreads();
    float* stg = reinterpret_cast<float*>(smem);
    const int g = lane >> 2, tq = lane & 3;
    #pragma unroll
    for (int mf = 0; mf < 4; mf++) {
        float s0 = 0.f, s1 = 0.f;
        int lr0 = wm + mf*16 + g, lr1 = lr0 + 8;
        #pragma unroll
        for (int nf = 0; nf < 4; nf++) {
            int cb = wn + nf*8 + tq*2;
            float e00 = __expf(acc[mf][nf][0] * 0.125f);
            float e01 = __expf(acc[mf][nf][1] * 0.125f);
            float e10 = __expf(acc[mf][nf][2] * 0.125f);
            float e11 = __expf(acc[mf][nf][3] * 0.125f);
            s0 += e00 + e01; s1 += e10 + e11;
            stg[lr0 * 132 + cb] = e00; stg[lr0 * 132 + cb + 1] = e01;
            stg[lr1 * 132 + cb] = e10; stg[lr1 * 132 + cb + 1] = e11;
        }
        s0 += __shfl_xor_sync(0xffffffffu, s0, 1);
        s0 += __shfl_xor_sync(0xffffffffu, s0, 2);
        s1 += __shfl_xor_sync(0xffffffffu, s1, 1);
        s1 += __shfl_xor_sync(0xffffffffu, s1, 2);
        if (tq == 0) {
            srow[lr0][wid & 3] = s0;
            srow[lr1][wid & 3] = s1;
        }
    }
    __syncthreads();

    float* ap = attn + (long)z * LL * LL + (long)row0 * LL + col0;
    for (int i = tid; i < 128 * 32; i += 256) {
        int row = i >> 5, q = i & 31;
        float4 v = *reinterpret_cast<const float4*>(stg + row * 132 + q * 4);
        *reinterpret_cast<float4*>(ap + (long)row * LL + q * 4) = v;
    }
    if (tid < 128) {
        float t = srow[tid][0] + srow[tid][1] + srow[tid][2] + srow[tid][3];
        part[((long)z * LL + row0 + tid) * 16 + blockIdx.x] = t;
    }
}

// ---------------------------------------------------------------------------
// Row reciprocal
// ---------------------------------------------------------------------------
__global__ void __launch_bounds__(256) rowinv_kernel(const float* __restrict__ part,
                                                     float* __restrict__ rinv) {
    long i = (long)blockIdx.x * 256 + threadIdx.x;
    float s = 0.f;
    #pragma unroll
    for (int t = 0; t < 16; t++) s += part[i * 16 + t];
    rinv[i] = 1.0f / s;
}

// ---------------------------------------------------------------------------
// AV, 3-stage cp.async: normalize attn chunk (smem-staged), write back, split,
// MMA vs Vt. Block 128x64. Dyn smem: Ah(10240) Al(10240),
// stages at 20480 + s*26624: ATTN f32(16384) Vh(5120) Vl(5120)
// ---------------------------------------------------------------------------
#define AV_DSMEM (20480 + 3*26624)
__global__ void __launch_bounds__(256) av_mma_kernel(
    float* __restrict__ attn, const float* __restrict__ rinv)
{
    extern __shared__ __align__(16) char smem[];
    __shared__ float rvs[128];
    const uint32_t sb = smem_u32(smem);
    const int tid = threadIdx.x, wid = tid >> 5, lane = tid & 31;
    const int z = blockIdx.y;
    const int row0 = blockIdx.x * 128;
    const int wm = (wid >> 2) * 64, wn = (wid & 3) * 16;

    float* ab = attn + (long)z * LL * LL + (long)row0 * LL;
    const __nv_bfloat16* vh = g_Vth + (long)z * LL * DHH;
    const __nv_bfloat16* vl = g_Vtl + (long)z * LL * DHH;

    if (tid < 128) rvs[tid] = rinv[(long)z * LL + row0 + tid];

    float acc[4][2][4];
    #pragma unroll
    for (int i = 0; i < 4; i++)
        #pragma unroll
        for (int j = 0; j < 2; j++)
            #pragma unroll
            for (int q = 0; q < 4; q++) acc[i][j][q] = 0.f;

    const uint32_t AH = sb, AL = sb + 10240;
    const int NC = LL / 32;   // 64

    // prologue stages 0,1
    #pragma unroll
    for (int p = 0; p < 2; p++) {
        uint32_t s = sb + 20480 + p * 26624;
        long goff = (long)p * 32;
        for (int i = tid; i < 1024; i += 256) {
            int row = i >> 3, q = i & 7;
            cp16(s + row * 128 + q * 16, ab + (long)row * LL + goff + q * 4);
        }
        load32_async(vh + goff, LL, 64, s + 16384, tid);
        load32_async(vl + goff, LL, 64, s + 21504, tid);
        CP_COMMIT();
    }

    for (int c = 0; c < NC; c++) {
        CP_WAIT1();
        __syncthreads();
        if (c + 2 < NC) {
            uint32_t sn = sb + 20480 + ((c + 2) % 3) * 26624;
            long goff = (long)(c + 2) * 32;
            for (int i = tid; i < 1024; i += 256) {
                int row = i >> 3, q = i & 7;
                cp16(sn + row * 128 + q * 16, ab + (long)row * LL + goff + q * 4);
            }
            load32_async(vh + goff, LL, 64, sn + 16384, tid);
            load32_async(vl + goff, LL, 64, sn + 21504, tid);
            CP_COMMIT();
        } else {
            CP_COMMIT();
        }
        uint32_t sc = sb + 20480 + (c % 3) * 26624;
        char* stg = smem + (sc - sb);

        for (int i = tid; i < 1024; i += 256) {
            int row = i >> 3, q = i & 7;
            float4 v = *reinterpret_cast<const float4*>(stg + row * 128 + q * 16);
            float r = rvs[row];
            v.x *= r; v.y *= r; v.z *= r; v.w *= r;
            *reinterpret_cast<float4*>(ab + (long)row * LL + (long)c * 32 + q * 4) = v;
            unsigned short h0,h1,h2,h3,l0,l1,l2,l3;
            split2(v.x,h0,l0); split2(v.y,h1,l1); split2(v.z,h2,l2); split2(v.w,h3,l3);
            uint2 uh, ul;
            uh.x = (uint32_t)h0 | ((uint32_t)h1 << 16);
            uh.y = (uint32_t)h2 | ((uint32_t)h3 << 16);
            ul.x = (uint32_t)l0 | ((uint32_t)l1 << 16);
            ul.y = (uint32_t)l2 | ((uint32_t)l3 << 16);
            *reinterpret_cast<uint2*>(smem + row * 80 + q * 8)         = uh;
            *reinterpret_cast<uint2*>(smem + 10240 + row * 80 + q * 8) = ul;
        }
        __syncthreads();

        uint32_t sBh = sc + 16384, sBl = sc + 21504;
        #pragma unroll
        for (int ks = 0; ks < 32; ks += 16) {
            uint32_t ah[4][4], al[4][4], bh[4], bl[4];
            #pragma unroll
            for (int mf = 0; mf < 4; mf++) {
                lda_frag(ah[mf], AH, wm + mf*16, ks, lane);
                lda_frag(al[mf], AL, wm + mf*16, ks, lane);
            }
            ldb_frag(bh, sBh, wn, ks, lane);
            ldb_frag(bl, sBl, wn, ks, lane);
            #pragma unroll
            for (int mf = 0; mf < 4; mf++)
                #pragma unroll
                for (int nf = 0; nf < 2; nf++) {
                    MMA_BF16(acc[mf][nf], ah[mf], bh[nf*2], bh[nf*2+1]);
                    MMA_BF16(acc[mf][nf], ah[mf], bl[nf*2], bl[nf*2+1]);
                    MMA_BF16(acc[mf][nf], al[mf], bh[nf*2], bh[nf*2+1]);
                }
        }
    }

    const int g = lane >> 2, tq = lane & 3;
    #pragma unroll
    for (int mf = 0; mf < 4; mf++)
        #pragma unroll
        for (int nf = 0; nf < 2; nf++) {
            long r0 = row0 + wm + mf*16 + g, r1 = r0 + 8;
            int cb = wn + nf*8 + tq*2;
            unsigned short h0,h1,l0,l1;
            long o0 = (long)z * LL * DHH + r0 * 64 + cb;
            long o1 = (long)z * LL * DHH + r1 * 64 + cb;
            split2(acc[mf][nf][0], h0, l0); split2(acc[mf][nf][1], h1, l1);
            *reinterpret_cast<uint32_t*>(g_ctxh + o0) = (uint32_t)h0 | ((uint32_t)h1<<16);
            *reinterpret_cast<uint32_t*>(g_ctxl + o0) = (uint32_t)l0 | ((uint32_t)l1<<16);
            split2(acc[mf][nf][2], h0, l0); split2(acc[mf][nf][3], h1, l1);
            *reinterpret_cast<uint32_t*>(g_ctxh + o1) = (uint32_t)h0 | ((uint32_t)h1<<16);
            *reinterpret_cast<uint32_t*>(g_ctxl + o1) = (uint32_t)l0 | ((uint32_t)l1<<16);
        }
}

// ---------------------------------------------------------------------------
// Residual + LayerNorm
// ---------------------------------------------------------------------------
__device__ __forceinline__ float warp_sum(float v) {
    #pragma unroll
    for (int o = 16; o > 0; o >>= 1) v += __shfl_xor_sync(0xffffffffu, v, o);
    return v;
}

__global__ void __launch_bounds__(256) ln_kernel(
    const float* __restrict__ resid,
    const float* __restrict__ gamma, const float* __restrict__ beta,
    float* __restrict__ out)
{
    const long row = blockIdx.x;
    const int tid = threadIdx.x, lane = tid & 31, wid = tid >> 5;
    __shared__ float red[8];

    float4 x = reinterpret_cast<const float4*>(g_proj + row * DD)[tid];
    float4 r = reinterpret_cast<const float4*>(resid + row * DD)[tid];
    x.x += r.x; x.y += r.y; x.z += r.z; x.w += r.w;

    float s = warp_sum(x.x + x.y + x.z + x.w);
    if (lane == 0) red[wid] = s;
    __syncthreads();
    if (wid == 0) {
        float t = (lane < 8) ? red[lane] : 0.f;
        t = warp_sum(t);
        if (lane == 0) red[0] = t;
    }
    __syncthreads();
    const float mu = red[0] * (1.0f / DD);
    __syncthreads();

    float dx = x.x - mu, dy = x.y - mu, dz = x.z - mu, dw = x.w - mu;
    float ss = warp_sum(dx*dx + dy*dy + dz*dz + dw*dw);
    if (lane == 0) red[wid] = ss;
    __syncthreads();
    if (wid == 0) {
        float t = (lane < 8) ? red[lane] : 0.f;
        t = warp_sum(t);
        if (lane == 0) red[0] = t;
    }
    __syncthreads();
    const float rs = rsqrtf(red[0] * (1.0f / DD) + LN_EPS);

    float4 gm = reinterpret_cast<const float4*>(gamma)[tid];
    float4 be = reinterpret_cast<const float4*>(beta)[tid];
    float4 o;
    o.x = dx * rs * gm.x + be.x;
    o.y = dy * rs * gm.y + be.y;
    o.z = dz * rs * gm.z + be.z;
    o.w = dw * rs * gm.w + be.w;
    reinterpret_cast<float4*>(out + row * DD)[tid] = o;
}

// ---------------------------------------------------------------------------
// Launch
// ---------------------------------------------------------------------------
extern "C" void kernel_launch(void* const* d_in, const int* in_sizes, int n_in,
                              void* d_out, int out_size)
{
    const float* query = (const float*)d_in[0];
    const float* key   = (const float*)d_in[1];
    const float* value = (const float*)d_in[2];
    const float* Wq = (const float*)d_in[3];
    const float* bq = (const float*)d_in[4];
    const float* Wk = (const float*)d_in[5];
    const float* bk = (const float*)d_in[6];
    const float* Wv = (const float*)d_in[7];
    const float* bv = (const float*)d_in[8];
    const float* Wo = (const float*)d_in[9];
    const float* bo = (const float*)d_in[10];
    const float* gamma = (const float*)d_in[11];
    const float* beta  = (const float*)d_in[12];

    float* out  = (float*)d_out;
    float* attn = out + OUT_ELEMS;

    float *part, *rinv;
    cudaGetSymbolAddress((void**)&part, g_part);
    cudaGetSymbolAddress((void**)&rinv, g_rinv);

    cudaFuncSetAttribute(qkv_proj_kernel,   cudaFuncAttributeMaxDynamicSharedMemorySize, PROJ_DSMEM);
    cudaFuncSetAttribute(outproj_kernel,    cudaFuncAttributeMaxDynamicSharedMemorySize, PROJ_DSMEM);
    cudaFuncSetAttribute(scores_mma_kernel, cudaFuncAttributeMaxDynamicSharedMemorySize, SC_DSMEM);
    cudaFuncSetAttribute(av_mma_kernel,     cudaFuncAttributeMaxDynamicSharedMemorySize, AV_DSMEM);

    // 1) fp32 -> split bf16 (merged)
    dim3 gsi(OUT_ELEMS / 1024, 3);
    split_inputs_kernel<<<gsi, 256>>>(query, key, value);
    dim3 gsw(DD * DD / 1024, 4);
    split_weights_kernel<<<gsw, 256>>>(Wq, Wk, Wv, Wo);

    // 2) Fused Q/K/V projections
    dim3 gp(DD/128, MROWS/128, 3);
    qkv_proj_kernel<<<gp, 256, PROJ_DSMEM>>>(bq, bk, bv);

    // 3) Scores + exp + partial sums
    dim3 gs(LL/128, LL/128, BH);
    scores_mma_kernel<<<gs, 256, SC_DSMEM>>>(attn, part);

    // 4) Row reciprocals
    rowinv_kernel<<<(BH*LL)/256, 256>>>(part, rinv);

    // 5) AV (normalizes attention in place, writes ctx hi/lo)
    dim3 ga(LL/128, BH);
    av_mma_kernel<<<ga, 256, AV_DSMEM>>>(attn, rinv);

    // 6) Out projection + residual + LN
    dim3 go(DD/128, MROWS/128);
    outproj_kernel<<<go, 256, PROJ_DSMEM>>>(bo);
    ln_kernel<<<MROWS, 256>>>(query, gamma, beta, out);
}